// round 2
// baseline (speedup 1.0000x reference)
#include <cuda_runtime.h>

// ---------------- problem constants ----------------
#define IMG_H 256
#define IMG_W 256
#define BATCH 4
#define HW (IMG_H * IMG_W)

// conv tiling: 32x32 pixel tile, threads (8,32); each thread: 4 x-pixels, 8 couts
#define TW 32
#define TH 32
#define COUT_PT 8
#define CIN_CHUNK 4
#define SROW 35            // smem row stride (conflict-free for 4tx+35*ty pattern)

// ---------------- scratch (device globals; no allocs allowed) ----------------
__device__ float g_fea1[BATCH * 64 * HW];
__device__ float g_bufA[BATCH * 64 * HW];
__device__ float g_bufB[BATCH * 64 * HW];
__device__ float g_bufC[BATCH * 64 * HW];
__device__ float g_core[BATCH * 75 * HW];
__device__ float g_res [BATCH * 3  * HW];

// ---------------- generic fused 3x3 SAME conv ----------------
// out = act( beta*out + conv(in, wgt[:, cinw0:cinw0+CinBuf]) + bias ) + addsrc + addsrc2
// ACT: 0 none, 1 relu, 2 leaky-relu(0.1)
template <int ACT>
__global__ __launch_bounds__(256, 2)
void conv3x3_kernel(const float* __restrict__ in, const float* __restrict__ wgt,
                    const float* __restrict__ bias, const float* __restrict__ addsrc,
                    const float* __restrict__ addsrc2,
                    float* __restrict__ out,
                    int CinBuf,   // channels in the input buffer
                    int CinW,     // channel stride of the weight tensor
                    int cinw0,    // starting input-channel offset inside the weight tensor
                    int Cout,     // output channels
                    int beta)     // 1 -> accumulate into existing out
{
    __shared__ float s_in[CIN_CHUNK][TH + 2][SROW];
    __shared__ float s_w[COUT_PT][CIN_CHUNK][12];   // 9 taps padded to 12

    const int tx = threadIdx.x;          // 0..7
    const int ty = threadIdx.y;          // 0..31
    const int tid = ty * 8 + tx;
    const int cx = tx * 4;               // base column within tile
    const int w0 = blockIdx.x * TW;
    const int by = blockIdx.y;           // 8 tiles/image * 4 images
    const int b  = by >> 3;
    const int h0 = (by & 7) * TH;
    const int coBase = blockIdx.z * COUT_PT;

    float acc[COUT_PT * 4];
#pragma unroll
    for (int i = 0; i < COUT_PT * 4; i++) acc[i] = 0.f;

    for (int cin0 = 0; cin0 < CinBuf; cin0 += CIN_CHUNK) {
        const int cc = min(CIN_CHUNK, CinBuf - cin0);
        __syncthreads();

        // ---- load input halo tile (cc channels), (TH+2) x (TW+2) each ----
        for (int ci = 0; ci < cc; ci++) {
            const float* ip = in + (size_t)(b * CinBuf + cin0 + ci) * HW;
            for (int j = tid; j < (TH + 2) * (TW + 2); j += 256) {
                int r = j / (TW + 2);
                int c = j - r * (TW + 2);
                int hh = h0 - 1 + r;
                int ww = w0 - 1 + c;
                float v = 0.f;
                if (hh >= 0 && hh < IMG_H && ww >= 0 && ww < IMG_W) v = ip[hh * IMG_W + ww];
                s_in[ci][r][c] = v;
            }
        }
        // ---- load weights (COUT_PT x cc x 9, zero-padded) ----
        for (int j = tid; j < COUT_PT * CIN_CHUNK * 9; j += 256) {
            int co = j / (CIN_CHUNK * 9);
            int rem = j - co * (CIN_CHUNK * 9);
            int ci = rem / 9;
            int k = rem - ci * 9;
            float v = 0.f;
            int cog = coBase + co;
            if (ci < cc && cog < Cout)
                v = wgt[((size_t)cog * CinW + (cinw0 + cin0 + ci)) * 9 + k];
            s_w[co][ci][k] = v;
        }
        __syncthreads();

        // ---- compute: 4 pixels x COUT_PT couts per thread ----
        auto body = [&](int ci) {
            float v[3][6];
#pragma unroll
            for (int r = 0; r < 3; r++)
#pragma unroll
                for (int c = 0; c < 6; c++)
                    v[r][c] = s_in[ci][ty + r][cx + c];
#pragma unroll
            for (int co = 0; co < COUT_PT; co++) {
                float4 wa = *(const float4*)&s_w[co][ci][0];
                float4 wb = *(const float4*)&s_w[co][ci][4];
                float  w8 = s_w[co][ci][8];
#pragma unroll
                for (int p = 0; p < 4; p++) {
                    float s = acc[co * 4 + p];
                    s += v[0][p + 0] * wa.x;
                    s += v[0][p + 1] * wa.y;
                    s += v[0][p + 2] * wa.z;
                    s += v[1][p + 0] * wa.w;
                    s += v[1][p + 1] * wb.x;
                    s += v[1][p + 2] * wb.y;
                    s += v[2][p + 0] * wb.z;
                    s += v[2][p + 1] * wb.w;
                    s += v[2][p + 2] * w8;
                    acc[co * 4 + p] = s;
                }
            }
        };
        if (cc == CIN_CHUNK) {
#pragma unroll
            for (int ci = 0; ci < CIN_CHUNK; ci++) body(ci);
        } else {
            for (int ci = 0; ci < cc; ci++) body(ci);
        }
    }

    // ---- epilogue: float4 per (co) ----
    const int hh = h0 + ty;
    const int ww = w0 + cx;
#pragma unroll
    for (int co = 0; co < COUT_PT; co++) {
        int cog = coBase + co;
        if (cog >= Cout) break;
        size_t idx = (size_t)(b * Cout + cog) * HW + (size_t)hh * IMG_W + ww;
        float4 v = make_float4(acc[co * 4 + 0], acc[co * 4 + 1],
                               acc[co * 4 + 2], acc[co * 4 + 3]);
        if (beta) {
            float4 o = *(const float4*)&out[idx];
            v.x += o.x; v.y += o.y; v.z += o.z; v.w += o.w;
        }
        if (bias) {
            float bb = __ldg(&bias[cog]);
            v.x += bb; v.y += bb; v.z += bb; v.w += bb;
        }
        if (ACT == 1) {
            v.x = fmaxf(v.x, 0.f); v.y = fmaxf(v.y, 0.f);
            v.z = fmaxf(v.z, 0.f); v.w = fmaxf(v.w, 0.f);
        } else if (ACT == 2) {
            v.x = (v.x >= 0.f) ? v.x : 0.1f * v.x;
            v.y = (v.y >= 0.f) ? v.y : 0.1f * v.y;
            v.z = (v.z >= 0.f) ? v.z : 0.1f * v.z;
            v.w = (v.w >= 0.f) ? v.w : 0.1f * v.w;
        }
        if (addsrc) {
            float4 a = *(const float4*)&addsrc[idx];
            v.x += a.x; v.y += a.y; v.z += a.z; v.w += a.w;
        }
        if (addsrc2) {
            float4 a = *(const float4*)&addsrc2[idx];
            v.x += a.x; v.y += a.y; v.z += a.z; v.w += a.w;
        }
        *(float4*)&out[idx] = v;
    }
}

// ---------------- KPN: per-pixel 5x5 kernels + residual ----------------
__global__ void kpn_kernel(const float* __restrict__ x, const float* __restrict__ core,
                           const float* __restrict__ res, float* __restrict__ out)
{
    int idx = blockIdx.x * blockDim.x + threadIdx.x;
    if (idx >= BATCH * 3 * HW) return;
    int w = idx & (IMG_W - 1);
    int h = (idx >> 8) & (IMG_H - 1);
    int bc = idx >> 16;             // b*3 + c
    int c = bc % 3;
    int b = bc / 3;

    const float* xp = x + (size_t)bc * HW;
    const float* cp = core + (size_t)(b * 75 + c * 25) * HW + h * IMG_W + w;

    float s = 0.f;
#pragma unroll
    for (int ky = 0; ky < 5; ky++) {
        int hh = h + ky - 2;
#pragma unroll
        for (int kx = 0; kx < 5; kx++) {
            int ww = w + kx - 2;
            float xv = (hh >= 0 && hh < IMG_H && ww >= 0 && ww < IMG_W) ? xp[hh * IMG_W + ww] : 0.f;
            s += xv * cp[(ky * 5 + kx) * HW];
        }
    }
    out[idx] = s + res[idx];
}

// ---------------- host-side helper ----------------
static void launch_conv(const float* in, const float* wgt, const float* bias,
                        const float* addsrc, const float* addsrc2, float* out,
                        int CinBuf, int CinW, int cinw0, int Cout, int beta, int act)
{
    dim3 grid(IMG_W / TW, (IMG_H / TH) * BATCH, (Cout + COUT_PT - 1) / COUT_PT);
    dim3 blk(8, 32);
    if (act == 0)
        conv3x3_kernel<0><<<grid, blk>>>(in, wgt, bias, addsrc, addsrc2, out, CinBuf, CinW, cinw0, Cout, beta);
    else if (act == 1)
        conv3x3_kernel<1><<<grid, blk>>>(in, wgt, bias, addsrc, addsrc2, out, CinBuf, CinW, cinw0, Cout, beta);
    else
        conv3x3_kernel<2><<<grid, blk>>>(in, wgt, bias, addsrc, addsrc2, out, CinBuf, CinW, cinw0, Cout, beta);
}

extern "C" void kernel_launch(void* const* d_in, const int* in_sizes, int n_in,
                              void* d_out, int out_size)
{
    const float* x       = (const float*)d_in[0];
    const float* w_first = (const float*)d_in[1];
    const float* b_first = (const float*)d_in[2];
    const float* w_trunk = (const float*)d_in[3];
    const float* b_trunk = (const float*)d_in[4];
    const float* c1_w    = (const float*)d_in[5];
    const float* c1_b    = (const float*)d_in[6];
    const float* c2_w1   = (const float*)d_in[7];
    const float* c2_b1   = (const float*)d_in[8];
    const float* c2_w2   = (const float*)d_in[9];
    const float* c2_b2   = (const float*)d_in[10];
    const float* c3_w1   = (const float*)d_in[11];
    const float* c3_b1   = (const float*)d_in[12];
    const float* c3_w2   = (const float*)d_in[13];
    const float* c3_b2   = (const float*)d_in[14];
    const float* c3_w3   = (const float*)d_in[15];
    const float* c3_b3   = (const float*)d_in[16];
    float* out = (float*)d_out;
    (void)in_sizes; (void)n_in; (void)out_size;

    float *fea1, *bufA, *bufB, *bufC, *core, *res;
    cudaGetSymbolAddress((void**)&fea1, g_fea1);
    cudaGetSymbolAddress((void**)&bufA, g_bufA);
    cudaGetSymbolAddress((void**)&bufB, g_bufB);
    cudaGetSymbolAddress((void**)&bufC, g_bufC);
    cudaGetSymbolAddress((void**)&core, g_core);
    cudaGetSymbolAddress((void**)&res,  g_res);

    // 1) fea1 = lrelu(conv_first(x))
    launch_conv(x, w_first, b_first, nullptr, nullptr, fea1, 3, 3, 0, 64, 0, 2);

    // 2) 16 residual blocks (ping-pong A/B, tmp C); fold the global residual
    //    (F += fea1) into the last block's epilogue.
    const float* cur = fea1;
    for (int i = 0; i < 16; i++) {
        const float* w1 = w_trunk + (size_t)(i * 2 + 0) * 64 * 64 * 9;
        const float* b1 = b_trunk + (size_t)(i * 2 + 0) * 64;
        const float* w2 = w_trunk + (size_t)(i * 2 + 1) * 64 * 64 * 9;
        const float* b2 = b_trunk + (size_t)(i * 2 + 1) * 64;
        float* dst = (i & 1) ? bufB : bufA;
        const float* extra = (i == 15) ? fea1 : nullptr;
        launch_conv(cur, w1, b1, nullptr, nullptr, bufC, 64, 64, 0, 64, 0, 1);  // T = relu(conv1(cur))
        launch_conv(bufC, w2, b2, cur, extra, dst, 64, 64, 0, 64, 0, 0);        // dst = conv2(T)+cur[+fea1]
        cur = dst;
    }
    float* F = (float*)cur;   // trunk output + global residual

    // 3) image-feature branch: t3 = conv(relu(conv(relu(conv(x)))))
    float* tA = (F == bufB) ? bufA : bufB;
    launch_conv(x,    c3_w1, c3_b1, nullptr, nullptr, tA,   3, 3, 0, 64, 0, 1);
    launch_conv(tA,   c3_w2, c3_b2, nullptr, nullptr, bufC, 64, 64, 0, 64, 0, 1);
    launch_conv(bufC, c3_w3, c3_b3, nullptr, nullptr, tA,   64, 64, 0, 64, 0, 0);  // t3 in tA

    // 4) residual branch: R1 = relu(conv(concat[t3, F], c2_w1)) -- two accumulating passes
    launch_conv(tA, c2_w1, nullptr, nullptr, nullptr, bufC, 64, 128, 0,  64, 0, 0);
    launch_conv(F,  c2_w1, c2_b1,  nullptr, nullptr, bufC, 64, 128, 64, 64, 1, 1);
    // residual = conv(R1, c2_w2)
    launch_conv(bufC, c2_w2, c2_b2, nullptr, nullptr, res, 64, 64, 0, 3, 0, 0);

    // 5) core = conv(concat[t3, F], c1_w) -- two accumulating passes
    launch_conv(tA, c1_w, nullptr, nullptr, nullptr, core, 64, 128, 0,  75, 0, 0);
    launch_conv(F,  c1_w, c1_b,   nullptr, nullptr, core, 64, 128, 64, 75, 1, 0);

    // 6) KPN apply + residual
    kpn_kernel<<<(BATCH * 3 * HW + 255) / 256, 256>>>(x, core, res, out);
}

// round 4
// speedup vs baseline: 1.0878x; 1.0878x over previous
#include <cuda_runtime.h>

// ---------------- problem constants ----------------
#define IMG_H 256
#define IMG_W 256
#define BATCH 4
#define HW (IMG_H * IMG_W)

// conv tiling: 32x32 pixel tile, threads (8,32); each thread: 4 x-pixels, 4 couts
#define TW 32
#define TH 32
#define COUT_PT 4
#define CIN_CHUNK 4
#define SROW 40            // smem row stride in floats: 16B-aligned, conflict-free

// ---------------- scratch (device globals; no allocs allowed) ----------------
__device__ float g_fea1[BATCH * 64 * HW];
__device__ float g_bufA[BATCH * 64 * HW];
__device__ float g_bufB[BATCH * 64 * HW];
__device__ float g_bufC[BATCH * 64 * HW];
__device__ float g_core[BATCH * 75 * HW];
__device__ float g_res [BATCH * 3  * HW];

// ---------------- generic fused 3x3 SAME conv ----------------
// out = act( beta*out + conv(in, wgt[:, cinw0:cinw0+CinBuf]) + bias ) + addsrc + addsrc2
// ACT: 0 none, 1 relu, 2 leaky-relu(0.1)
template <int ACT>
__global__ __launch_bounds__(256, 4)
void conv3x3_kernel(const float* __restrict__ in, const float* __restrict__ wgt,
                    const float* __restrict__ bias, const float* __restrict__ addsrc,
                    const float* __restrict__ addsrc2,
                    float* __restrict__ out,
                    int CinBuf,   // channels in the input buffer
                    int CinW,     // channel stride of the weight tensor
                    int cinw0,    // starting input-channel offset inside the weight tensor
                    int Cout,     // output channels
                    int beta)     // 1 -> accumulate into existing out
{
    __shared__ float s_in[CIN_CHUNK][TH + 2][SROW];
    __shared__ float s_w[COUT_PT][CIN_CHUNK][12];   // 9 taps padded to 12

    const int tx = threadIdx.x;          // 0..7
    const int ty = threadIdx.y;          // 0..31
    const int tid = ty * 8 + tx;
    const int cx = tx * 4;               // base column within tile
    const int w0 = blockIdx.x * TW;
    const int by = blockIdx.y;           // 8 tiles/image * 4 images
    const int b  = by >> 3;
    const int h0 = (by & 7) * TH;
    const int coBase = blockIdx.z * COUT_PT;

    float acc[COUT_PT * 4];
#pragma unroll
    for (int i = 0; i < COUT_PT * 4; i++) acc[i] = 0.f;

    for (int cin0 = 0; cin0 < CinBuf; cin0 += CIN_CHUNK) {
        const int cc = min(CIN_CHUNK, CinBuf - cin0);
        __syncthreads();

        // ---- load input halo tile (cc channels), (TH+2) x (TW+2) each ----
        for (int ci = 0; ci < cc; ci++) {
            const float* ip = in + (size_t)(b * CinBuf + cin0 + ci) * HW;
            for (int j = tid; j < (TH + 2) * (TW + 2); j += 256) {
                int r = j / (TW + 2);
                int c = j - r * (TW + 2);
                int hh = h0 - 1 + r;
                int ww = w0 - 1 + c;
                float v = 0.f;
                if (hh >= 0 && hh < IMG_H && ww >= 0 && ww < IMG_W) v = ip[hh * IMG_W + ww];
                s_in[ci][r][c] = v;
            }
        }
        // ---- load weights (COUT_PT x cc x 9, zero-padded) ----
        if (tid < COUT_PT * CIN_CHUNK * 9) {
            int j = tid;
            int co = j / (CIN_CHUNK * 9);
            int rem = j - co * (CIN_CHUNK * 9);
            int ci = rem / 9;
            int k = rem - ci * 9;
            float v = 0.f;
            int cog = coBase + co;
            if (ci < cc && cog < Cout)
                v = wgt[((size_t)cog * CinW + (cinw0 + cin0 + ci)) * 9 + k];
            s_w[co][ci][k] = v;
        }
        __syncthreads();

        // ---- compute: 4 pixels x COUT_PT couts per thread ----
        auto body = [&](int ci) {
            // vector loads: 6 consecutive floats per row = float4 + float2
            float v[3][6];
#pragma unroll
            for (int r = 0; r < 3; r++) {
                const float* rp = &s_in[ci][ty + r][cx];
                float4 a = *(const float4*)rp;
                float2 bseg = *(const float2*)(rp + 4);
                v[r][0] = a.x; v[r][1] = a.y; v[r][2] = a.z; v[r][3] = a.w;
                v[r][4] = bseg.x; v[r][5] = bseg.y;
            }
#pragma unroll
            for (int co = 0; co < COUT_PT; co++) {
                float4 wa = *(const float4*)&s_w[co][ci][0];
                float4 wb = *(const float4*)&s_w[co][ci][4];
                float  w8 = s_w[co][ci][8];
#pragma unroll
                for (int p = 0; p < 4; p++) {
                    float s = acc[co * 4 + p];
                    s += v[0][p + 0] * wa.x;
                    s += v[0][p + 1] * wa.y;
                    s += v[0][p + 2] * wa.z;
                    s += v[1][p + 0] * wa.w;
                    s += v[1][p + 1] * wb.x;
                    s += v[1][p + 2] * wb.y;
                    s += v[2][p + 0] * wb.z;
                    s += v[2][p + 1] * wb.w;
                    s += v[2][p + 2] * w8;
                    acc[co * 4 + p] = s;
                }
            }
        };
        if (cc == CIN_CHUNK) {
#pragma unroll
            for (int ci = 0; ci < CIN_CHUNK; ci++) body(ci);
        } else {
            for (int ci = 0; ci < cc; ci++) body(ci);
        }
    }

    // ---- epilogue: float4 per (co) ----
    const int hh = h0 + ty;
    const int ww = w0 + cx;
#pragma unroll
    for (int co = 0; co < COUT_PT; co++) {
        int cog = coBase + co;
        if (cog >= Cout) break;
        size_t idx = (size_t)(b * Cout + cog) * HW + (size_t)hh * IMG_W + ww;
        float4 v = make_float4(acc[co * 4 + 0], acc[co * 4 + 1],
                               acc[co * 4 + 2], acc[co * 4 + 3]);
        if (beta) {
            float4 o = *(const float4*)&out[idx];
            v.x += o.x; v.y += o.y; v.z += o.z; v.w += o.w;
        }
        if (bias) {
            float bb = __ldg(&bias[cog]);
            v.x += bb; v.y += bb; v.z += bb; v.w += bb;
        }
        if (ACT == 1) {
            v.x = fmaxf(v.x, 0.f); v.y = fmaxf(v.y, 0.f);
            v.z = fmaxf(v.z, 0.f); v.w = fmaxf(v.w, 0.f);
        } else if (ACT == 2) {
            v.x = (v.x >= 0.f) ? v.x : 0.1f * v.x;
            v.y = (v.y >= 0.f) ? v.y : 0.1f * v.y;
            v.z = (v.z >= 0.f) ? v.z : 0.1f * v.z;
            v.w = (v.w >= 0.f) ? v.w : 0.1f * v.w;
        }
        if (addsrc) {
            float4 a = *(const float4*)&addsrc[idx];
            v.x += a.x; v.y += a.y; v.z += a.z; v.w += a.w;
        }
        if (addsrc2) {
            float4 a = *(const float4*)&addsrc2[idx];
            v.x += a.x; v.y += a.y; v.z += a.z; v.w += a.w;
        }
        *(float4*)&out[idx] = v;
    }
}

// ---------------- KPN: per-pixel 5x5 kernels + residual ----------------
__global__ void kpn_kernel(const float* __restrict__ x, const float* __restrict__ core,
                           const float* __restrict__ res, float* __restrict__ out)
{
    int idx = blockIdx.x * blockDim.x + threadIdx.x;
    if (idx >= BATCH * 3 * HW) return;
    int w = idx & (IMG_W - 1);
    int h = (idx >> 8) & (IMG_H - 1);
    int bc = idx >> 16;             // b*3 + c
    int c = bc % 3;
    int b = bc / 3;

    const float* xp = x + (size_t)bc * HW;
    const float* cp = core + (size_t)(b * 75 + c * 25) * HW + h * IMG_W + w;

    float s = 0.f;
#pragma unroll
    for (int ky = 0; ky < 5; ky++) {
        int hh = h + ky - 2;
#pragma unroll
        for (int kx = 0; kx < 5; kx++) {
            int ww = w + kx - 2;
            float xv = (hh >= 0 && hh < IMG_H && ww >= 0 && ww < IMG_W) ? xp[hh * IMG_W + ww] : 0.f;
            s += xv * cp[(ky * 5 + kx) * HW];
        }
    }
    out[idx] = s + res[idx];
}

// ---------------- host-side helper ----------------
static void launch_conv(const float* in, const float* wgt, const float* bias,
                        const float* addsrc, const float* addsrc2, float* out,
                        int CinBuf, int CinW, int cinw0, int Cout, int beta, int act)
{
    dim3 grid(IMG_W / TW, (IMG_H / TH) * BATCH, (Cout + COUT_PT - 1) / COUT_PT);
    dim3 blk(8, 32);
    if (act == 0)
        conv3x3_kernel<0><<<grid, blk>>>(in, wgt, bias, addsrc, addsrc2, out, CinBuf, CinW, cinw0, Cout, beta);
    else if (act == 1)
        conv3x3_kernel<1><<<grid, blk>>>(in, wgt, bias, addsrc, addsrc2, out, CinBuf, CinW, cinw0, Cout, beta);
    else
        conv3x3_kernel<2><<<grid, blk>>>(in, wgt, bias, addsrc, addsrc2, out, CinBuf, CinW, cinw0, Cout, beta);
}

extern "C" void kernel_launch(void* const* d_in, const int* in_sizes, int n_in,
                              void* d_out, int out_size)
{
    const float* x       = (const float*)d_in[0];
    const float* w_first = (const float*)d_in[1];
    const float* b_first = (const float*)d_in[2];
    const float* w_trunk = (const float*)d_in[3];
    const float* b_trunk = (const float*)d_in[4];
    const float* c1_w    = (const float*)d_in[5];
    const float* c1_b    = (const float*)d_in[6];
    const float* c2_w1   = (const float*)d_in[7];
    const float* c2_b1   = (const float*)d_in[8];
    const float* c2_w2   = (const float*)d_in[9];
    const float* c2_b2   = (const float*)d_in[10];
    const float* c3_w1   = (const float*)d_in[11];
    const float* c3_b1   = (const float*)d_in[12];
    const float* c3_w2   = (const float*)d_in[13];
    const float* c3_b2   = (const float*)d_in[14];
    const float* c3_w3   = (const float*)d_in[15];
    const float* c3_b3   = (const float*)d_in[16];
    float* out = (float*)d_out;
    (void)in_sizes; (void)n_in; (void)out_size;

    float *fea1, *bufA, *bufB, *bufC, *core, *res;
    cudaGetSymbolAddress((void**)&fea1, g_fea1);
    cudaGetSymbolAddress((void**)&bufA, g_bufA);
    cudaGetSymbolAddress((void**)&bufB, g_bufB);
    cudaGetSymbolAddress((void**)&bufC, g_bufC);
    cudaGetSymbolAddress((void**)&core, g_core);
    cudaGetSymbolAddress((void**)&res,  g_res);

    // 1) fea1 = lrelu(conv_first(x))
    launch_conv(x, w_first, b_first, nullptr, nullptr, fea1, 3, 3, 0, 64, 0, 2);

    // 2) 16 residual blocks (ping-pong A/B, tmp C); fold the global residual
    //    (F += fea1) into the last block's epilogue.
    const float* cur = fea1;
    for (int i = 0; i < 16; i++) {
        const float* w1 = w_trunk + (size_t)(i * 2 + 0) * 64 * 64 * 9;
        const float* b1 = b_trunk + (size_t)(i * 2 + 0) * 64;
        const float* w2 = w_trunk + (size_t)(i * 2 + 1) * 64 * 64 * 9;
        const float* b2 = b_trunk + (size_t)(i * 2 + 1) * 64;
        float* dst = (i & 1) ? bufB : bufA;
        const float* extra = (i == 15) ? fea1 : nullptr;
        launch_conv(cur, w1, b1, nullptr, nullptr, bufC, 64, 64, 0, 64, 0, 1);  // T = relu(conv1(cur))
        launch_conv(bufC, w2, b2, cur, extra, dst, 64, 64, 0, 64, 0, 0);        // dst = conv2(T)+cur[+fea1]
        cur = dst;
    }
    float* F = (float*)cur;   // trunk output + global residual

    // 3) image-feature branch: t3 = conv(relu(conv(relu(conv(x)))))
    float* tA = (F == bufB) ? bufA : bufB;
    launch_conv(x,    c3_w1, c3_b1, nullptr, nullptr, tA,   3, 3, 0, 64, 0, 1);
    launch_conv(tA,   c3_w2, c3_b2, nullptr, nullptr, bufC, 64, 64, 0, 64, 0, 1);
    launch_conv(bufC, c3_w3, c3_b3, nullptr, nullptr, tA,   64, 64, 0, 64, 0, 0);  // t3 in tA

    // 4) residual branch: R1 = relu(conv(concat[t3, F], c2_w1)) -- two accumulating passes
    launch_conv(tA, c2_w1, nullptr, nullptr, nullptr, bufC, 64, 128, 0,  64, 0, 0);
    launch_conv(F,  c2_w1, c2_b1,  nullptr, nullptr, bufC, 64, 128, 64, 64, 1, 1);
    // residual = conv(R1, c2_w2)
    launch_conv(bufC, c2_w2, c2_b2, nullptr, nullptr, res, 64, 64, 0, 3, 0, 0);

    // 5) core = conv(concat[t3, F], c1_w) -- two accumulating passes
    launch_conv(tA, c1_w, nullptr, nullptr, nullptr, core, 64, 128, 0,  75, 0, 0);
    launch_conv(F,  c1_w, c1_b,   nullptr, nullptr, core, 64, 128, 64, 75, 1, 0);

    // 6) KPN apply + residual
    kpn_kernel<<<(BATCH * 3 * HW + 255) / 256, 256>>>(x, core, res, out);
}

// round 9
// speedup vs baseline: 1.3723x; 1.2616x over previous
#include <cuda_runtime.h>

// ---------------- problem constants ----------------
#define IMG_H 256
#define IMG_W 256
#define BATCH 4
#define HW (IMG_H * IMG_W)

// conv tiling: 32x16 pixel tile, threads (16,16); each thread: 2 x-pixels, 8 couts
#define TW 32
#define TH 16
#define COUT_PT 8
#define CIN_CHUNK 8
#define SROW 36            // smem row stride in floats (144B, 16B-aligned)

// ---------------- scratch (device globals; no allocs allowed) ----------------
__device__ float g_fea1[BATCH * 64 * HW];
__device__ float g_bufA[BATCH * 64 * HW];
__device__ float g_bufB[BATCH * 64 * HW];
__device__ float g_bufC[BATCH * 64 * HW];
__device__ float g_core[BATCH * 75 * HW];
__device__ float g_res [BATCH * 3  * HW];

// ---------------- generic fused 3x3 SAME conv ----------------
// out = act( beta*out + conv(in, wgt[:, cinw0:cinw0+CinBuf]) + bias ) + addsrc + addsrc2
// ACT: 0 none, 1 relu, 2 leaky-relu(0.1)
template <int ACT>
__global__ __launch_bounds__(256, 4)
void conv3x3_kernel(const float* __restrict__ in, const float* __restrict__ wgt,
                    const float* __restrict__ bias, const float* __restrict__ addsrc,
                    const float* __restrict__ addsrc2,
                    float* __restrict__ out,
                    int CinBuf,   // channels in the input buffer
                    int CinW,     // channel stride of the weight tensor
                    int cinw0,    // starting input-channel offset inside the weight tensor
                    int Cout,     // output channels
                    int beta)     // 1 -> accumulate into existing out
{
    __shared__ float s_in[CIN_CHUNK][TH + 2][SROW];
    __shared__ float s_w[COUT_PT][CIN_CHUNK][12];   // 9 taps padded to 12

    const int tx = threadIdx.x;          // 0..15
    const int ty = threadIdx.y;          // 0..15
    const int tid = ty * 16 + tx;
    const int cx = tx * 2;               // base column within tile (8B-aligned in smem)
    const int w0 = blockIdx.x * TW;
    const int by = blockIdx.y;           // 16 tiles/image * 4 images
    const int b  = by >> 4;
    const int h0 = (by & 15) * TH;
    const int coBase = blockIdx.z * COUT_PT;

    float acc[COUT_PT * 2];
#pragma unroll
    for (int i = 0; i < COUT_PT * 2; i++) acc[i] = 0.f;

    const int nChunks = (CinBuf + CIN_CHUNK - 1) / CIN_CHUNK;
    for (int ch = 0; ch < nChunks; ch++) {
        const int cin0 = ch * CIN_CHUNK;
        const int cc = min(CIN_CHUNK, CinBuf - cin0);
        __syncthreads();

        // ---- load input halo tile (cc channels), 18 x 34 each ----
        for (int ci = 0; ci < cc; ci++) {
            const float* ip = in + (size_t)(b * CinBuf + cin0 + ci) * HW;
            for (int j = tid; j < (TH + 2) * (TW + 2); j += 256) {
                int r = j / (TW + 2);
                int c = j - r * (TW + 2);
                int hh = h0 - 1 + r;
                int ww = w0 - 1 + c;
                float v = 0.f;
                if (hh >= 0 && hh < IMG_H && ww >= 0 && ww < IMG_W) v = ip[hh * IMG_W + ww];
                s_in[ci][r][c] = v;
            }
        }
        // ---- load weights (COUT_PT x cc x 9, zero-padded) ----
        for (int j = tid; j < COUT_PT * CIN_CHUNK * 9; j += 256) {
            int co = j / (CIN_CHUNK * 9);
            int rem = j - co * (CIN_CHUNK * 9);
            int ci = rem / 9;
            int k = rem - ci * 9;
            float v = 0.f;
            int cog = coBase + co;
            if (ci < cc && cog < Cout)
                v = wgt[((size_t)cog * CinW + (cinw0 + cin0 + ci)) * 9 + k];
            s_w[co][ci][k] = v;
        }
        __syncthreads();

        // ---- compute: 2 pixels x 8 couts per thread ----
        auto body = [&](int ci) {
            // 3 rows x 4 consecutive floats each, via 2x LDS.64 (8B-aligned)
            float2 r0a = *(const float2*)&s_in[ci][ty + 0][cx];
            float2 r0b = *(const float2*)&s_in[ci][ty + 0][cx + 2];
            float2 r1a = *(const float2*)&s_in[ci][ty + 1][cx];
            float2 r1b = *(const float2*)&s_in[ci][ty + 1][cx + 2];
            float2 r2a = *(const float2*)&s_in[ci][ty + 2][cx];
            float2 r2b = *(const float2*)&s_in[ci][ty + 2][cx + 2];
            float r0x = r0a.x, r0y = r0a.y, r0z = r0b.x, r0w = r0b.y;
            float r1x = r1a.x, r1y = r1a.y, r1z = r1b.x, r1w = r1b.y;
            float r2x = r2a.x, r2y = r2a.y, r2z = r2b.x, r2w = r2b.y;
            const float* wp = &s_w[0][ci][0];
#pragma unroll
            for (int co = 0; co < COUT_PT; co++) {
                float4 wa = *(const float4*)(wp + co * CIN_CHUNK * 12 + 0);
                float4 wb = *(const float4*)(wp + co * CIN_CHUNK * 12 + 4);
                float  w8 = *(wp + co * CIN_CHUNK * 12 + 8);
                float s0 = acc[co * 2 + 0];
                float s1 = acc[co * 2 + 1];
                s0 += r0x * wa.x;  s1 += r0y * wa.x;
                s0 += r0y * wa.y;  s1 += r0z * wa.y;
                s0 += r0z * wa.z;  s1 += r0w * wa.z;
                s0 += r1x * wa.w;  s1 += r1y * wa.w;
                s0 += r1y * wb.x;  s1 += r1z * wb.x;
                s0 += r1z * wb.y;  s1 += r1w * wb.y;
                s0 += r2x * wb.z;  s1 += r2y * wb.z;
                s0 += r2y * wb.w;  s1 += r2z * wb.w;
                s0 += r2z * w8;    s1 += r2w * w8;
                acc[co * 2 + 0] = s0;
                acc[co * 2 + 1] = s1;
            }
        };
        if (cc == CIN_CHUNK) {
#pragma unroll
            for (int ci = 0; ci < CIN_CHUNK; ci++) body(ci);
        } else {
            for (int ci = 0; ci < cc; ci++) body(ci);
        }
    }

    // ---- epilogue: float2 per (co), 8B-aligned ----
    const int hh = h0 + ty;
    const int ww = w0 + cx;
#pragma unroll
    for (int co = 0; co < COUT_PT; co++) {
        int cog = coBase + co;
        if (cog >= Cout) break;
        size_t idx = (size_t)(b * Cout + cog) * HW + (size_t)hh * IMG_W + ww;
        float2 v = make_float2(acc[co * 2 + 0], acc[co * 2 + 1]);
        if (beta) {
            float2 o = *(const float2*)&out[idx];
            v.x += o.x; v.y += o.y;
        }
        if (bias) {
            float bb = __ldg(&bias[cog]);
            v.x += bb; v.y += bb;
        }
        if (ACT == 1) {
            v.x = fmaxf(v.x, 0.f); v.y = fmaxf(v.y, 0.f);
        } else if (ACT == 2) {
            v.x = (v.x >= 0.f) ? v.x : 0.1f * v.x;
            v.y = (v.y >= 0.f) ? v.y : 0.1f * v.y;
        }
        if (addsrc) {
            float2 a = *(const float2*)&addsrc[idx];
            v.x += a.x; v.y += a.y;
        }
        if (addsrc2) {
            float2 a = *(const float2*)&addsrc2[idx];
            v.x += a.x; v.y += a.y;
        }
        *(float2*)&out[idx] = v;
    }
}

// ---------------- KPN: per-pixel 5x5 kernels + residual ----------------
__global__ void kpn_kernel(const float* __restrict__ x, const float* __restrict__ core,
                           const float* __restrict__ res, float* __restrict__ out)
{
    int idx = blockIdx.x * blockDim.x + threadIdx.x;
    if (idx >= BATCH * 3 * HW) return;
    int w = idx & (IMG_W - 1);
    int h = (idx >> 8) & (IMG_H - 1);
    int bc = idx >> 16;             // b*3 + c
    int c = bc % 3;
    int b = bc / 3;

    const float* xp = x + (size_t)bc * HW;
    const float* cp = core + (size_t)(b * 75 + c * 25) * HW + h * IMG_W + w;

    float s = 0.f;
#pragma unroll
    for (int ky = 0; ky < 5; ky++) {
        int hh = h + ky - 2;
#pragma unroll
        for (int kx = 0; kx < 5; kx++) {
            int ww = w + kx - 2;
            float xv = (hh >= 0 && hh < IMG_H && ww >= 0 && ww < IMG_W) ? xp[hh * IMG_W + ww] : 0.f;
            s += xv * cp[(ky * 5 + kx) * HW];
        }
    }
    out[idx] = s + res[idx];
}

// ---------------- host-side helper ----------------
static void launch_conv(const float* in, const float* wgt, const float* bias,
                        const float* addsrc, const float* addsrc2, float* out,
                        int CinBuf, int CinW, int cinw0, int Cout, int beta, int act)
{
    dim3 grid(IMG_W / TW, (IMG_H / TH) * BATCH, (Cout + COUT_PT - 1) / COUT_PT);
    dim3 blk(16, 16);
    if (act == 0)
        conv3x3_kernel<0><<<grid, blk>>>(in, wgt, bias, addsrc, addsrc2, out, CinBuf, CinW, cinw0, Cout, beta);
    else if (act == 1)
        conv3x3_kernel<1><<<grid, blk>>>(in, wgt, bias, addsrc, addsrc2, out, CinBuf, CinW, cinw0, Cout, beta);
    else
        conv3x3_kernel<2><<<grid, blk>>>(in, wgt, bias, addsrc, addsrc2, out, CinBuf, CinW, cinw0, Cout, beta);
}

extern "C" void kernel_launch(void* const* d_in, const int* in_sizes, int n_in,
                              void* d_out, int out_size)
{
    const float* x       = (const float*)d_in[0];
    const float* w_first = (const float*)d_in[1];
    const float* b_first = (const float*)d_in[2];
    const float* w_trunk = (const float*)d_in[3];
    const float* b_trunk = (const float*)d_in[4];
    const float* c1_w    = (const float*)d_in[5];
    const float* c1_b    = (const float*)d_in[6];
    const float* c2_w1   = (const float*)d_in[7];
    const float* c2_b1   = (const float*)d_in[8];
    const float* c2_w2   = (const float*)d_in[9];
    const float* c2_b2   = (const float*)d_in[10];
    const float* c3_w1   = (const float*)d_in[11];
    const float* c3_b1   = (const float*)d_in[12];
    const float* c3_w2   = (const float*)d_in[13];
    const float* c3_b2   = (const float*)d_in[14];
    const float* c3_w3   = (const float*)d_in[15];
    const float* c3_b3   = (const float*)d_in[16];
    float* out = (float*)d_out;
    (void)in_sizes; (void)n_in; (void)out_size;

    float *fea1, *bufA, *bufB, *bufC, *core, *res;
    cudaGetSymbolAddress((void**)&fea1, g_fea1);
    cudaGetSymbolAddress((void**)&bufA, g_bufA);
    cudaGetSymbolAddress((void**)&bufB, g_bufB);
    cudaGetSymbolAddress((void**)&bufC, g_bufC);
    cudaGetSymbolAddress((void**)&core, g_core);
    cudaGetSymbolAddress((void**)&res,  g_res);

    // 1) fea1 = lrelu(conv_first(x))
    launch_conv(x, w_first, b_first, nullptr, nullptr, fea1, 3, 3, 0, 64, 0, 2);

    // 2) 16 residual blocks (ping-pong A/B, tmp C); fold the global residual
    //    (F += fea1) into the last block's epilogue.
    const float* cur = fea1;
    for (int i = 0; i < 16; i++) {
        const float* w1 = w_trunk + (size_t)(i * 2 + 0) * 64 * 64 * 9;
        const float* b1 = b_trunk + (size_t)(i * 2 + 0) * 64;
        const float* w2 = w_trunk + (size_t)(i * 2 + 1) * 64 * 64 * 9;
        const float* b2 = b_trunk + (size_t)(i * 2 + 1) * 64;
        float* dst = (i & 1) ? bufB : bufA;
        const float* extra = (i == 15) ? fea1 : nullptr;
        launch_conv(cur, w1, b1, nullptr, nullptr, bufC, 64, 64, 0, 64, 0, 1);  // T = relu(conv1(cur))
        launch_conv(bufC, w2, b2, cur, extra, dst, 64, 64, 0, 64, 0, 0);        // dst = conv2(T)+cur[+fea1]
        cur = dst;
    }
    float* F = (float*)cur;   // trunk output + global residual

    // 3) image-feature branch: t3 = conv(relu(conv(relu(conv(x)))))
    float* tA = (F == bufB) ? bufA : bufB;
    launch_conv(x,    c3_w1, c3_b1, nullptr, nullptr, tA,   3, 3, 0, 64, 0, 1);
    launch_conv(tA,   c3_w2, c3_b2, nullptr, nullptr, bufC, 64, 64, 0, 64, 0, 1);
    launch_conv(bufC, c3_w3, c3_b3, nullptr, nullptr, tA,   64, 64, 0, 64, 0, 0);  // t3 in tA

    // 4) residual branch: R1 = relu(conv(concat[t3, F], c2_w1)) -- two accumulating passes
    launch_conv(tA, c2_w1, nullptr, nullptr, nullptr, bufC, 64, 128, 0,  64, 0, 0);
    launch_conv(F,  c2_w1, c2_b1,  nullptr, nullptr, bufC, 64, 128, 64, 64, 1, 1);
    // residual = conv(R1, c2_w2)
    launch_conv(bufC, c2_w2, c2_b2, nullptr, nullptr, res, 64, 64, 0, 3, 0, 0);

    // 5) core = conv(concat[t3, F], c1_w) -- two accumulating passes
    launch_conv(tA, c1_w, nullptr, nullptr, nullptr, core, 64, 128, 0,  75, 0, 0);
    launch_conv(F,  c1_w, c1_b,   nullptr, nullptr, core, 64, 128, 64, 75, 1, 0);

    // 6) KPN apply + residual
    kpn_kernel<<<(BATCH * 3 * HW + 255) / 256, 256>>>(x, core, res, out);
}

// round 12
// speedup vs baseline: 4.8464x; 3.5316x over previous
#include <cuda_runtime.h>
#include <cuda_bf16.h>
#include <cstdint>

// ================= problem constants =================
#define IMG 256
#define BATCH 4
#define HW 65536
#define NPIX 262144          // BATCH*HW

// ================= device scratch (no allocs) =================
// NHWC fp32 planes: 0=fea1 1=bufA 2=bufB 3=bufT
__device__ __align__(16) float g_nhwc[4][(size_t)NPIX * 64];
__device__ float g_core[(size_t)BATCH * 75 * HW];
__device__ float g_res [(size_t)BATCH * 3  * HW];
// fragment-ordered bf16 weights (u32 elements)
#define WF_TRUNK(j) ((size_t)(j) * 36864)
#define WF_C3W2  1179648
#define WF_C3W3  1216512
#define WF_C2W1  1253376
#define WF_C1    1327104
#define WF_C2W2  1419264
#define WF_TOTAL 1423872
__device__ __align__(16) unsigned g_wfrag[WF_TOTAL];

// ================= helpers =================
__device__ __forceinline__ unsigned smem_u32(const void* p) {
    unsigned a;
    asm("{ .reg .u64 t; cvta.to.shared.u64 t, %1; cvt.u32.u64 %0, t; }" : "=r"(a) : "l"(p));
    return a;
}
__device__ __forceinline__ unsigned pk(__nv_bfloat16 a, __nv_bfloat16 b) {
    return (unsigned)__bfloat16_as_ushort(a) | ((unsigned)__bfloat16_as_ushort(b) << 16);
}

// ================= weight prep: OIHW fp32 -> fragment-ordered bf16 =================
// u32 index = (((chunk*2 + term)*4 + kstep)*NT + ntile)*64 + lane*2 + r
// value: halves {B[k][n], B[k+1][n]} with n = ntile*8 + lane/4, k = kstep*16 + (lane%4)*2 + 8r
// chunk = src*9 + ky*3 + kx ; ci = src*64 + k ; term0=hi, term1=lo
__global__ void prep_w(const float* __restrict__ w, unsigned* __restrict__ dst,
                       int Cout, int CinW, int NT, int total)
{
    int idx = blockIdx.x * 256 + threadIdx.x;
    if (idx >= total) return;
    int lane2 = idx & 63;
    int lane = lane2 >> 1, r = lane2 & 1;
    int tmp = idx >> 6;
    int ntile = tmp % NT; tmp /= NT;
    int kstep = tmp & 3; tmp >>= 2;
    int term = tmp & 1;
    int chunk = tmp >> 1;
    int src = chunk / 9, t9 = chunk % 9, ky = t9 / 3, kx = t9 % 3;
    int n = ntile * 8 + (lane >> 2);
    int k = kstep * 16 + ((lane & 3) << 1) + 8 * r;
    int ci = src * 64 + k;
    float v0 = 0.f, v1 = 0.f;
    if (n < Cout) {
        if (ci < CinW)     v0 = w[(((size_t)n * CinW + ci) * 3 + ky) * 3 + kx];
        if (ci + 1 < CinW) v1 = w[(((size_t)n * CinW + ci + 1) * 3 + ky) * 3 + kx];
    }
    __nv_bfloat16 h0 = __float2bfloat16(v0), h1 = __float2bfloat16(v1);
    unsigned outv;
    if (term == 0) outv = pk(h0, h1);
    else outv = pk(__float2bfloat16(v0 - __bfloat162float(h0)),
                   __float2bfloat16(v1 - __bfloat162float(h1)));
    dst[idx] = outv;
}

// ================= tensor-core implicit-GEMM 3x3 conv (mma.sync bf16, 3-term) ======
// CTA: 128 pixels (half row) x NT*8 couts. 8 warps: 4 M x 2 N.
// in: NHWC fp32 (a0; a1 = second concat source or null)
// out: NHWC fp32 (outN) or NCHW fp32 (outC). Optional relu, 2 residual adds (NHWC).
template <int NT>
__global__ __launch_bounds__(256)
void tc_conv(const float* __restrict__ a0, const float* __restrict__ a1,
             const unsigned* __restrict__ wf, const float* __restrict__ bias,
             float* __restrict__ outN,
             const float* __restrict__ r0, const float* __restrict__ r1,
             float* __restrict__ outC, int Cout, int relu)
{
    constexpr int HNT = (NT + 1) / 2;          // ntiles per N-warp
    __shared__ __nv_bfloat16 sA[2][130][72];   // [hi/lo][slot][ci] stride 144B
    const int tid = threadIdx.x;
    const int lane = tid & 31, wid = tid >> 5;
    const int mw = wid & 3, nw = wid >> 2;
    const int t = blockIdx.x;
    const int b = t >> 9, rem = t & 511, y = rem >> 1, x0 = (rem & 1) << 7;
    const int nSrc = (a1 != nullptr) ? 2 : 1;

    float acc[2][HNT][4];
#pragma unroll
    for (int mt = 0; mt < 2; mt++)
#pragma unroll
        for (int j = 0; j < HNT; j++)
#pragma unroll
            for (int q = 0; q < 4; q++) acc[mt][j][q] = 0.f;

    for (int src = 0; src < nSrc; src++) {
        const float* ap = src ? a1 : a0;
        for (int ky = 0; ky < 3; ky++) {
            int yy = y + ky - 1;
            if (yy < 0 || yy >= IMG) continue;
            __syncthreads();
            // ---- load input row (slots 0..129 = x0-1 .. x0+128), hi/lo split ----
            const float* rowp = ap + ((size_t)b * HW + (size_t)yy * IMG) * 64;
            for (int i = tid; i < 130 * 16; i += 256) {
                int slot = i >> 4, cg = (i & 15) << 2;
                int ax = x0 - 1 + slot;
                float4 f = (ax >= 0 && ax < IMG)
                         ? *(const float4*)(rowp + (size_t)ax * 64 + cg)
                         : make_float4(0.f, 0.f, 0.f, 0.f);
                __nv_bfloat16 h0 = __float2bfloat16(f.x), h1 = __float2bfloat16(f.y);
                __nv_bfloat16 h2 = __float2bfloat16(f.z), h3 = __float2bfloat16(f.w);
                *(unsigned*)&sA[0][slot][cg]     = pk(h0, h1);
                *(unsigned*)&sA[0][slot][cg + 2] = pk(h2, h3);
                *(unsigned*)&sA[1][slot][cg]     = pk(__float2bfloat16(f.x - __bfloat162float(h0)),
                                                      __float2bfloat16(f.y - __bfloat162float(h1)));
                *(unsigned*)&sA[1][slot][cg + 2] = pk(__float2bfloat16(f.z - __bfloat162float(h2)),
                                                      __float2bfloat16(f.w - __bfloat162float(h3)));
            }
            __syncthreads();
            // ---- compute: 3 kx taps x 3 precision terms x 4 k-steps ----
            const int chunk0 = src * 9 + ky * 3;
#pragma unroll
            for (int kx = 0; kx < 3; kx++) {
#pragma unroll
                for (int term = 0; term < 3; term++) {
                    const int apl = (term == 2) ? 1 : 0;      // A plane: lo only for term 2
                    const int bt  = (term == 1) ? 1 : 0;      // B term: lo only for term 1
                    const unsigned* wfp = wf + (size_t)(((chunk0 + kx) * 2 + bt) * 4) * NT * 64;
#pragma unroll
                    for (int ks = 0; ks < 4; ks++) {
                        unsigned a[2][4];
#pragma unroll
                        for (int mt = 0; mt < 2; mt++) {
                            int slot = mw * 32 + mt * 16 + (lane & 15) + kx;
                            int kh = ks * 16 + ((lane >> 4) << 3);
                            unsigned addr = smem_u32(&sA[apl][slot][kh]);
                            asm volatile("ldmatrix.sync.aligned.m8n8.x4.shared.b16 "
                                         "{%0,%1,%2,%3}, [%4];"
                                         : "=r"(a[mt][0]), "=r"(a[mt][1]),
                                           "=r"(a[mt][2]), "=r"(a[mt][3])
                                         : "r"(addr));
                        }
#pragma unroll
                        for (int j = 0; j < HNT; j++) {
                            int nt = nw * HNT + j;
                            if (nt >= NT) break;
                            uint2 bf = *(const uint2*)(wfp + (size_t)(ks * NT + nt) * 64 + lane * 2);
#pragma unroll
                            for (int mt = 0; mt < 2; mt++) {
                                asm volatile(
                                    "mma.sync.aligned.m16n8k16.row.col.f32.bf16.bf16.f32 "
                                    "{%0,%1,%2,%3}, {%4,%5,%6,%7}, {%8,%9}, {%0,%1,%2,%3};"
                                    : "+f"(acc[mt][j][0]), "+f"(acc[mt][j][1]),
                                      "+f"(acc[mt][j][2]), "+f"(acc[mt][j][3])
                                    : "r"(a[mt][0]), "r"(a[mt][1]), "r"(a[mt][2]), "r"(a[mt][3]),
                                      "r"(bf.x), "r"(bf.y));
                            }
                        }
                    }
                }
            }
        }
    }

    // ---- epilogue ----
    const size_t pixB = (size_t)b * HW + (size_t)y * IMG + x0;
#pragma unroll
    for (int mt = 0; mt < 2; mt++) {
        int prow = mw * 32 + mt * 16 + (lane >> 2);
#pragma unroll
        for (int j = 0; j < HNT; j++) {
            int nt = nw * HNT + j;
            if (nt >= NT) break;
            int cout = nt * 8 + ((lane & 3) << 1);
            if (outN) {
                float2 bb = *(const float2*)&bias[cout];
                float v0 = acc[mt][j][0] + bb.x, v1 = acc[mt][j][1] + bb.y;
                float v2 = acc[mt][j][2] + bb.x, v3 = acc[mt][j][3] + bb.y;
                if (relu) {
                    v0 = fmaxf(v0, 0.f); v1 = fmaxf(v1, 0.f);
                    v2 = fmaxf(v2, 0.f); v3 = fmaxf(v3, 0.f);
                }
                size_t i0 = (pixB + prow) * 64 + cout;
                size_t i1 = (pixB + prow + 8) * 64 + cout;
                if (r0) {
                    float2 q = *(const float2*)&r0[i0]; v0 += q.x; v1 += q.y;
                    q = *(const float2*)&r0[i1]; v2 += q.x; v3 += q.y;
                }
                if (r1) {
                    float2 q = *(const float2*)&r1[i0]; v0 += q.x; v1 += q.y;
                    q = *(const float2*)&r1[i1]; v2 += q.x; v3 += q.y;
                }
                *(float2*)&outN[i0] = make_float2(v0, v1);
                *(float2*)&outN[i1] = make_float2(v2, v3);
            } else {
#pragma unroll
                for (int q = 0; q < 4; q++) {
                    int co = cout + (q & 1);
                    if (co >= Cout) continue;
                    int pr = prow + ((q >> 1) << 3);
                    float v = acc[mt][j][q] + __ldg(&bias[co]);
                    if (relu) v = fmaxf(v, 0.f);
                    outC[((size_t)(b * Cout + co)) * HW + (size_t)y * IMG + x0 + pr] = v;
                }
            }
        }
    }
}

// ================= SIMT conv (Cin=3 only), NHWC fp32 output =================
#define TWs 32
#define THs 16
#define COUT_PTs 8
template <int ACT>   // 1 relu, 2 lrelu(0.1)
__global__ __launch_bounds__(256, 4)
void conv3_simt(const float* __restrict__ in, const float* __restrict__ wgt,
                const float* __restrict__ bias, float* __restrict__ out)
{
    __shared__ float s_in[3][THs + 2][36];
    __shared__ float s_w[COUT_PTs][3][12];
    const int tx = threadIdx.x, ty = threadIdx.y;
    const int tid = ty * 16 + tx;
    const int cx = tx * 2;
    const int w0 = blockIdx.x * TWs;
    const int by = blockIdx.y;
    const int b = by >> 4;
    const int h0 = (by & 15) * THs;
    const int coBase = blockIdx.z * COUT_PTs;
    float acc[COUT_PTs * 2];
#pragma unroll
    for (int i = 0; i < COUT_PTs * 2; i++) acc[i] = 0.f;

    for (int ci = 0; ci < 3; ci++) {
        const float* ip = in + (size_t)(b * 3 + ci) * HW;
        for (int j = tid; j < (THs + 2) * (TWs + 2); j += 256) {
            int r = j / (TWs + 2), c = j - r * (TWs + 2);
            int hh = h0 - 1 + r, ww = w0 - 1 + c;
            float v = 0.f;
            if (hh >= 0 && hh < IMG && ww >= 0 && ww < IMG) v = ip[hh * IMG + ww];
            s_in[ci][r][c] = v;
        }
    }
    if (tid < COUT_PTs * 27) {
        int co = tid / 27, rem2 = tid % 27, ci = rem2 / 9, k = rem2 % 9;
        s_w[co][ci][k] = wgt[((size_t)(coBase + co) * 3 + ci) * 9 + k];
    }
    __syncthreads();

    for (int ci = 0; ci < 3; ci++) {
        float2 r0a = *(const float2*)&s_in[ci][ty + 0][cx];
        float2 r0b = *(const float2*)&s_in[ci][ty + 0][cx + 2];
        float2 r1a = *(const float2*)&s_in[ci][ty + 1][cx];
        float2 r1b = *(const float2*)&s_in[ci][ty + 1][cx + 2];
        float2 r2a = *(const float2*)&s_in[ci][ty + 2][cx];
        float2 r2b = *(const float2*)&s_in[ci][ty + 2][cx + 2];
#pragma unroll
        for (int co = 0; co < COUT_PTs; co++) {
            float4 wa = *(const float4*)&s_w[co][ci][0];
            float4 wb = *(const float4*)&s_w[co][ci][4];
            float w8 = s_w[co][ci][8];
            float s0 = acc[co * 2], s1 = acc[co * 2 + 1];
            s0 += r0a.x * wa.x;  s1 += r0a.y * wa.x;
            s0 += r0a.y * wa.y;  s1 += r0b.x * wa.y;
            s0 += r0b.x * wa.z;  s1 += r0b.y * wa.z;
            s0 += r1a.x * wa.w;  s1 += r1a.y * wa.w;
            s0 += r1a.y * wb.x;  s1 += r1b.x * wb.x;
            s0 += r1b.x * wb.y;  s1 += r1b.y * wb.y;
            s0 += r2a.x * wb.z;  s1 += r2a.y * wb.z;
            s0 += r2a.y * wb.w;  s1 += r2b.x * wb.w;
            s0 += r2b.x * w8;    s1 += r2b.y * w8;
            acc[co * 2] = s0; acc[co * 2 + 1] = s1;
        }
    }
    const int hh = h0 + ty, ww = w0 + cx;
    const size_t pix = (size_t)b * HW + (size_t)hh * IMG + ww;
#pragma unroll
    for (int co = 0; co < COUT_PTs; co++) {
        int cog = coBase + co;
        float v0 = acc[co * 2], v1 = acc[co * 2 + 1];
        float bb = __ldg(&bias[cog]);
        v0 += bb; v1 += bb;
        if (ACT == 1) { v0 = fmaxf(v0, 0.f); v1 = fmaxf(v1, 0.f); }
        else { v0 = (v0 >= 0.f) ? v0 : 0.1f * v0; v1 = (v1 >= 0.f) ? v1 : 0.1f * v1; }
        out[pix * 64 + cog] = v0;
        out[(pix + 1) * 64 + cog] = v1;
    }
}

// ================= KPN: per-pixel 5x5 kernels + residual =================
__global__ void kpn_kernel(const float* __restrict__ x, const float* __restrict__ core,
                           const float* __restrict__ res, float* __restrict__ out)
{
    int idx = blockIdx.x * blockDim.x + threadIdx.x;
    if (idx >= BATCH * 3 * HW) return;
    int w = idx & (IMG - 1);
    int h = (idx >> 8) & (IMG - 1);
    int bc = idx >> 16;
    int c = bc % 3, b = bc / 3;
    const float* xp = x + (size_t)bc * HW;
    const float* cp = core + (size_t)(b * 75 + c * 25) * HW + h * IMG + w;
    float s = 0.f;
#pragma unroll
    for (int ky = 0; ky < 5; ky++) {
        int hh = h + ky - 2;
#pragma unroll
        for (int kx = 0; kx < 5; kx++) {
            int ww = w + kx - 2;
            float xv = (hh >= 0 && hh < IMG && ww >= 0 && ww < IMG) ? xp[hh * IMG + ww] : 0.f;
            s += xv * cp[(ky * 5 + kx) * HW];
        }
    }
    out[idx] = s + res[idx];
}

// ================= host =================
extern "C" void kernel_launch(void* const* d_in, const int* in_sizes, int n_in,
                              void* d_out, int out_size)
{
    const float* x       = (const float*)d_in[0];
    const float* w_first = (const float*)d_in[1];
    const float* b_first = (const float*)d_in[2];
    const float* w_trunk = (const float*)d_in[3];
    const float* b_trunk = (const float*)d_in[4];
    const float* c1_w    = (const float*)d_in[5];
    const float* c1_b    = (const float*)d_in[6];
    const float* c2_w1   = (const float*)d_in[7];
    const float* c2_b1   = (const float*)d_in[8];
    const float* c2_w2   = (const float*)d_in[9];
    const float* c2_b2   = (const float*)d_in[10];
    const float* c3_w1   = (const float*)d_in[11];
    const float* c3_b1   = (const float*)d_in[12];
    const float* c3_w2   = (const float*)d_in[13];
    const float* c3_b2   = (const float*)d_in[14];
    const float* c3_w3   = (const float*)d_in[15];
    const float* c3_b3   = (const float*)d_in[16];
    float* out = (float*)d_out;
    (void)in_sizes; (void)n_in; (void)out_size;

    float *nhwc, *core, *res;
    unsigned* wf;
    cudaGetSymbolAddress((void**)&nhwc, g_nhwc);
    cudaGetSymbolAddress((void**)&core, g_core);
    cudaGetSymbolAddress((void**)&res,  g_res);
    cudaGetSymbolAddress((void**)&wf,   g_wfrag);
    const size_t PL = (size_t)NPIX * 64;
    float* fea = nhwc;
    float* bA  = nhwc + PL;
    float* bB  = nhwc + 2 * PL;
    float* bT  = nhwc + 3 * PL;

    // ---- weight prep (fragment-ordered bf16 hi/lo) ----
    for (int j = 0; j < 32; j++)
        prep_w<<<(36864 + 255) / 256, 256>>>(w_trunk + (size_t)j * 36864, wf + WF_TRUNK(j), 64, 64, 8, 36864);
    prep_w<<<(36864 + 255) / 256, 256>>>(c3_w2, wf + WF_C3W2, 64, 64, 8, 36864);
    prep_w<<<(36864 + 255) / 256, 256>>>(c3_w3, wf + WF_C3W3, 64, 64, 8, 36864);
    prep_w<<<(73728 + 255) / 256, 256>>>(c2_w1, wf + WF_C2W1, 64, 128, 8, 73728);
    prep_w<<<(92160 + 255) / 256, 256>>>(c1_w,  wf + WF_C1,   75, 128, 10, 92160);
    prep_w<<<(4608  + 255) / 256, 256>>>(c2_w2, wf + WF_C2W2,  3,  64,  1, 4608);

    dim3 sgrid(IMG / TWs, (IMG / THs) * BATCH, 8);
    dim3 sblk(16, 16);

    // 1) fea1 = lrelu(conv_first(x))
    conv3_simt<2><<<sgrid, sblk>>>(x, w_first, b_first, fea);

    // 2) 16 residual blocks on tensor cores
    float* cur = fea;
    for (int i = 0; i < 16; i++) {
        float* dst = (i & 1) ? bB : bA;
        const float* extra = (i == 15) ? fea : nullptr;
        tc_conv<8><<<2048, 256>>>(cur, nullptr, wf + WF_TRUNK(2 * i), b_trunk + (size_t)(2 * i) * 64,
                                  bT, nullptr, nullptr, nullptr, 64, 1);
        tc_conv<8><<<2048, 256>>>(bT, nullptr, wf + WF_TRUNK(2 * i + 1), b_trunk + (size_t)(2 * i + 1) * 64,
                                  dst, cur, extra, nullptr, 64, 0);
        cur = dst;
    }
    // cur = bB (i=15). free: bA, bT.

    // 3) image branch: t1 (SIMT) -> t2 -> t3
    conv3_simt<1><<<sgrid, sblk>>>(x, c3_w1, c3_b1, bT);
    tc_conv<8><<<2048, 256>>>(bT, nullptr, wf + WF_C3W2, c3_b2, bA, nullptr, nullptr, nullptr, 64, 1);
    tc_conv<8><<<2048, 256>>>(bA, nullptr, wf + WF_C3W3, c3_b3, bT, nullptr, nullptr, nullptr, 64, 0); // t3=bT

    // 4) R1 = relu(conv(concat[t3,F], c2_w1)) -> bA ; res = conv(R1, c2_w2) (NCHW)
    tc_conv<8><<<2048, 256>>>(bT, cur, wf + WF_C2W1, c2_b1, bA, nullptr, nullptr, nullptr, 64, 1);
    tc_conv<1><<<2048, 256>>>(bA, nullptr, wf + WF_C2W2, c2_b2, nullptr, nullptr, nullptr, res, 3, 0);

    // 5) core = conv(concat[t3,F], c1_w) (NCHW)
    tc_conv<10><<<2048, 256>>>(bT, cur, wf + WF_C1, c1_b, nullptr, nullptr, nullptr, core, 75, 0);

    // 6) KPN + residual
    kpn_kernel<<<(BATCH * 3 * HW + 255) / 256, 256>>>(x, core, res, out);
}

// round 14
// speedup vs baseline: 6.0930x; 1.2572x over previous
#include <cuda_runtime.h>
#include <cuda_bf16.h>
#include <cstdint>

// ================= problem constants =================
#define IMG 256
#define BATCH 4
#define HW 65536
#define NPIX 262144          // BATCH*HW

// ================= device scratch (no allocs) =================
// NHWC fp32 planes: 0=fea1 1=bufA 2=bufB 3=bufT
__device__ __align__(16) float g_nhwc[4][(size_t)NPIX * 64];
__device__ float g_core[(size_t)BATCH * 75 * HW];
__device__ float g_res [(size_t)BATCH * 3  * HW];
// fragment-ordered bf16 weights (u32 elements)
#define WF_TRUNK(j) ((size_t)(j) * 36864)
#define WF_C3W2  1179648
#define WF_C3W3  1216512
#define WF_C2W1  1253376
#define WF_C1    1327104
#define WF_C2W2  1419264
#define WF_TOTAL 1423872
__device__ __align__(16) unsigned g_wfrag[WF_TOTAL];

// ================= helpers =================
__device__ __forceinline__ unsigned smem_u32(const void* p) {
    unsigned a;
    asm("{ .reg .u64 t; cvta.to.shared.u64 t, %1; cvt.u32.u64 %0, t; }" : "=r"(a) : "l"(p));
    return a;
}
__device__ __forceinline__ unsigned pk(__nv_bfloat16 a, __nv_bfloat16 b) {
    return (unsigned)__bfloat16_as_ushort(a) | ((unsigned)__bfloat16_as_ushort(b) << 16);
}
#define MMA_BF16(acc, a, b0, b1)                                              \
    asm volatile(                                                             \
        "mma.sync.aligned.m16n8k16.row.col.f32.bf16.bf16.f32 "               \
        "{%0,%1,%2,%3}, {%4,%5,%6,%7}, {%8,%9}, {%0,%1,%2,%3};"              \
        : "+f"((acc)[0]), "+f"((acc)[1]), "+f"((acc)[2]), "+f"((acc)[3])      \
        : "r"((a)[0]), "r"((a)[1]), "r"((a)[2]), "r"((a)[3]),                 \
          "r"(b0), "r"(b1))

// ================= weight prep: OIHW fp32 -> fragment-ordered bf16 =================
// u32 index = (((chunk*2 + term)*4 + kstep)*NT + ntile)*64 + lane*2 + r
// value: halves {B[k][n], B[k+1][n]} with n = ntile*8 + lane/4, k = kstep*16 + (lane%4)*2 + 8r
// chunk = src*9 + ky*3 + kx ; ci = src*64 + k ; term0=hi, term1=lo
__global__ void prep_w(const float* __restrict__ w, unsigned* __restrict__ dst,
                       int Cout, int CinW, int NT, int total)
{
    int idx = blockIdx.x * 256 + threadIdx.x;
    if (idx >= total) return;
    int lane2 = idx & 63;
    int lane = lane2 >> 1, r = lane2 & 1;
    int tmp = idx >> 6;
    int ntile = tmp % NT; tmp /= NT;
    int kstep = tmp & 3; tmp >>= 2;
    int term = tmp & 1;
    int chunk = tmp >> 1;
    int src = chunk / 9, t9 = chunk % 9, ky = t9 / 3, kx = t9 % 3;
    int n = ntile * 8 + (lane >> 2);
    int k = kstep * 16 + ((lane & 3) << 1) + 8 * r;
    int ci = src * 64 + k;
    float v0 = 0.f, v1 = 0.f;
    if (n < Cout) {
        if (ci < CinW)     v0 = w[(((size_t)n * CinW + ci) * 3 + ky) * 3 + kx];
        if (ci + 1 < CinW) v1 = w[(((size_t)n * CinW + ci + 1) * 3 + ky) * 3 + kx];
    }
    __nv_bfloat16 h0 = __float2bfloat16(v0), h1 = __float2bfloat16(v1);
    unsigned outv;
    if (term == 0) outv = pk(h0, h1);
    else outv = pk(__float2bfloat16(v0 - __bfloat162float(h0)),
                   __float2bfloat16(v1 - __bfloat162float(h1)));
    dst[idx] = outv;
}

// ======== 2-row tensor-core implicit-GEMM 3x3 conv (mma.sync bf16, 3-term) ========
// CTA: 2 output rows x 128 pixels x 64 couts. 8 warps: 4 M x 2 N.
// Each input row passes through smem ONCE and feeds both output rows.
__global__ __launch_bounds__(256, 2)
void tc_conv2(const float* __restrict__ a0, const float* __restrict__ a1,
              const unsigned* __restrict__ wf, const float* __restrict__ bias,
              float* __restrict__ outN,
              const float* __restrict__ r0, const float* __restrict__ r1, int relu)
{
    constexpr int NT = 8, HNT = 4;
    __shared__ __nv_bfloat16 sA[2][130][72];   // [hi/lo][slot][ci] stride 144B
    const int tid = threadIdx.x;
    const int lane = tid & 31, wid = tid >> 5;
    const int mw = wid & 3, nw = wid >> 2;
    const int t = blockIdx.x;
    const int b = t >> 8, rem = t & 255;
    const int y0 = (rem >> 1) << 1, x0 = (rem & 1) << 7;
    const int nSrc = (a1 != nullptr) ? 2 : 1;

    float acc[2][2][HNT][4];                   // [outrow][mt][nt][4]
#pragma unroll
    for (int o = 0; o < 2; o++)
#pragma unroll
        for (int mt = 0; mt < 2; mt++)
#pragma unroll
            for (int j = 0; j < HNT; j++)
#pragma unroll
                for (int q = 0; q < 4; q++) acc[o][mt][j][q] = 0.f;

    for (int src = 0; src < nSrc; src++) {
        const float* ap = src ? a1 : a0;
        for (int r = y0 - 1; r <= y0 + 2; r++) {
            if (r < 0 || r >= IMG) continue;
            __syncthreads();
            // ---- fill smem with input row r (slots 0..129 = x0-1..x0+128), hi/lo ----
            const float* rowp = ap + ((size_t)b * HW + (size_t)r * IMG) * 64;
            for (int i = tid; i < 130 * 16; i += 256) {
                int slot = i >> 4, cg = (i & 15) << 2;
                int ax = x0 - 1 + slot;
                float4 f = (ax >= 0 && ax < IMG)
                         ? *(const float4*)(rowp + (size_t)ax * 64 + cg)
                         : make_float4(0.f, 0.f, 0.f, 0.f);
                __nv_bfloat16 h0 = __float2bfloat16(f.x), h1 = __float2bfloat16(f.y);
                __nv_bfloat16 h2 = __float2bfloat16(f.z), h3 = __float2bfloat16(f.w);
                *(unsigned*)&sA[0][slot][cg]     = pk(h0, h1);
                *(unsigned*)&sA[0][slot][cg + 2] = pk(h2, h3);
                *(unsigned*)&sA[1][slot][cg]     = pk(__float2bfloat16(f.x - __bfloat162float(h0)),
                                                      __float2bfloat16(f.y - __bfloat162float(h1)));
                *(unsigned*)&sA[1][slot][cg + 2] = pk(__float2bfloat16(f.z - __bfloat162float(h2)),
                                                      __float2bfloat16(f.w - __bfloat162float(h3)));
            }
            __syncthreads();
            // which output rows does row r feed?
            const int ky0 = r - y0 + 1;          // tap for outrow 0 (>=0 always)
            const int ky1 = r - y0;              // tap for outrow 1 (<=2 always)
            const bool v0 = (ky0 <= 2);
            const bool v1 = (ky1 >= 0);
#pragma unroll
            for (int kx = 0; kx < 3; kx++) {
#pragma unroll
                for (int ks = 0; ks < 4; ks++) {
                    // ---- load A fragments once: hi and lo planes, both m-tiles ----
                    unsigned Ah[2][4], Al[2][4];
#pragma unroll
                    for (int mt = 0; mt < 2; mt++) {
                        int slot = mw * 32 + mt * 16 + (lane & 15) + kx;
                        int kh = ks * 16 + ((lane >> 4) << 3);
                        unsigned ah = smem_u32(&sA[0][slot][kh]);
                        asm volatile("ldmatrix.sync.aligned.m8n8.x4.shared.b16 "
                                     "{%0,%1,%2,%3}, [%4];"
                                     : "=r"(Ah[mt][0]), "=r"(Ah[mt][1]),
                                       "=r"(Ah[mt][2]), "=r"(Ah[mt][3]) : "r"(ah));
                        unsigned al = smem_u32(&sA[1][slot][kh]);
                        asm volatile("ldmatrix.sync.aligned.m8n8.x4.shared.b16 "
                                     "{%0,%1,%2,%3}, [%4];"
                                     : "=r"(Al[mt][0]), "=r"(Al[mt][1]),
                                       "=r"(Al[mt][2]), "=r"(Al[mt][3]) : "r"(al));
                    }
                    // ---- MMA blocks for each valid output row ----
#pragma unroll
                    for (int o = 0; o < 2; o++) {
                        if (o == 0 ? !v0 : !v1) continue;
                        const int chunk = src * 9 + (o == 0 ? ky0 : ky1) * 3 + kx;
                        const unsigned* wh = wf + ((size_t)((chunk * 2 + 0) * 4 + ks) * NT) * 64;
                        const unsigned* wl = wf + ((size_t)((chunk * 2 + 1) * 4 + ks) * NT) * 64;
#pragma unroll
                        for (int j = 0; j < HNT; j++) {
                            int nt = nw * HNT + j;
                            uint2 bh = *(const uint2*)(wh + (size_t)nt * 64 + lane * 2);
                            uint2 bl = *(const uint2*)(wl + (size_t)nt * 64 + lane * 2);
#pragma unroll
                            for (int mt = 0; mt < 2; mt++) {
                                MMA_BF16(acc[o][mt][j], Ah[mt], bh.x, bh.y);
                                MMA_BF16(acc[o][mt][j], Ah[mt], bl.x, bl.y);
                                MMA_BF16(acc[o][mt][j], Al[mt], bh.x, bh.y);
                            }
                        }
                    }
                }
            }
        }
    }

    // ---- epilogue: both output rows ----
#pragma unroll
    for (int o = 0; o < 2; o++) {
        const size_t pixB = (size_t)b * HW + (size_t)(y0 + o) * IMG + x0;
#pragma unroll
        for (int mt = 0; mt < 2; mt++) {
            int prow = mw * 32 + mt * 16 + (lane >> 2);
#pragma unroll
            for (int j = 0; j < HNT; j++) {
                int nt = nw * HNT + j;
                int cout = nt * 8 + ((lane & 3) << 1);
                float2 bb = *(const float2*)&bias[cout];
                float v0 = acc[o][mt][j][0] + bb.x, v1 = acc[o][mt][j][1] + bb.y;
                float v2 = acc[o][mt][j][2] + bb.x, v3 = acc[o][mt][j][3] + bb.y;
                if (relu) {
                    v0 = fmaxf(v0, 0.f); v1 = fmaxf(v1, 0.f);
                    v2 = fmaxf(v2, 0.f); v3 = fmaxf(v3, 0.f);
                }
                size_t i0 = (pixB + prow) * 64 + cout;
                size_t i1 = (pixB + prow + 8) * 64 + cout;
                if (r0) {
                    float2 q = *(const float2*)&r0[i0]; v0 += q.x; v1 += q.y;
                    q = *(const float2*)&r0[i1]; v2 += q.x; v3 += q.y;
                }
                if (r1) {
                    float2 q = *(const float2*)&r1[i0]; v0 += q.x; v1 += q.y;
                    q = *(const float2*)&r1[i1]; v2 += q.x; v3 += q.y;
                }
                *(float2*)&outN[i0] = make_float2(v0, v1);
                *(float2*)&outN[i1] = make_float2(v2, v3);
            }
        }
    }
}

// ======== 1-row variant (NCHW outputs: core/res), proven in R12 ========
template <int NT>
__global__ __launch_bounds__(256)
void tc_conv(const float* __restrict__ a0, const float* __restrict__ a1,
             const unsigned* __restrict__ wf, const float* __restrict__ bias,
             const float* __restrict__ r0, const float* __restrict__ r1,
             float* __restrict__ outC, int Cout, int relu)
{
    constexpr int HNT = (NT + 1) / 2;
    __shared__ __nv_bfloat16 sA[2][130][72];
    const int tid = threadIdx.x;
    const int lane = tid & 31, wid = tid >> 5;
    const int mw = wid & 3, nw = wid >> 2;
    const int t = blockIdx.x;
    const int b = t >> 9, rem = t & 511, y = rem >> 1, x0 = (rem & 1) << 7;
    const int nSrc = (a1 != nullptr) ? 2 : 1;

    float acc[2][HNT][4];
#pragma unroll
    for (int mt = 0; mt < 2; mt++)
#pragma unroll
        for (int j = 0; j < HNT; j++)
#pragma unroll
            for (int q = 0; q < 4; q++) acc[mt][j][q] = 0.f;

    for (int src = 0; src < nSrc; src++) {
        const float* ap = src ? a1 : a0;
        for (int ky = 0; ky < 3; ky++) {
            int yy = y + ky - 1;
            if (yy < 0 || yy >= IMG) continue;
            __syncthreads();
            const float* rowp = ap + ((size_t)b * HW + (size_t)yy * IMG) * 64;
            for (int i = tid; i < 130 * 16; i += 256) {
                int slot = i >> 4, cg = (i & 15) << 2;
                int ax = x0 - 1 + slot;
                float4 f = (ax >= 0 && ax < IMG)
                         ? *(const float4*)(rowp + (size_t)ax * 64 + cg)
                         : make_float4(0.f, 0.f, 0.f, 0.f);
                __nv_bfloat16 h0 = __float2bfloat16(f.x), h1 = __float2bfloat16(f.y);
                __nv_bfloat16 h2 = __float2bfloat16(f.z), h3 = __float2bfloat16(f.w);
                *(unsigned*)&sA[0][slot][cg]     = pk(h0, h1);
                *(unsigned*)&sA[0][slot][cg + 2] = pk(h2, h3);
                *(unsigned*)&sA[1][slot][cg]     = pk(__float2bfloat16(f.x - __bfloat162float(h0)),
                                                      __float2bfloat16(f.y - __bfloat162float(h1)));
                *(unsigned*)&sA[1][slot][cg + 2] = pk(__float2bfloat16(f.z - __bfloat162float(h2)),
                                                      __float2bfloat16(f.w - __bfloat162float(h3)));
            }
            __syncthreads();
            const int chunk0 = src * 9 + ky * 3;
#pragma unroll
            for (int kx = 0; kx < 3; kx++) {
#pragma unroll
                for (int ks = 0; ks < 4; ks++) {
                    unsigned Ah[2][4], Al[2][4];
#pragma unroll
                    for (int mt = 0; mt < 2; mt++) {
                        int slot = mw * 32 + mt * 16 + (lane & 15) + kx;
                        int kh = ks * 16 + ((lane >> 4) << 3);
                        unsigned ah = smem_u32(&sA[0][slot][kh]);
                        asm volatile("ldmatrix.sync.aligned.m8n8.x4.shared.b16 "
                                     "{%0,%1,%2,%3}, [%4];"
                                     : "=r"(Ah[mt][0]), "=r"(Ah[mt][1]),
                                       "=r"(Ah[mt][2]), "=r"(Ah[mt][3]) : "r"(ah));
                        unsigned al = smem_u32(&sA[1][slot][kh]);
                        asm volatile("ldmatrix.sync.aligned.m8n8.x4.shared.b16 "
                                     "{%0,%1,%2,%3}, [%4];"
                                     : "=r"(Al[mt][0]), "=r"(Al[mt][1]),
                                       "=r"(Al[mt][2]), "=r"(Al[mt][3]) : "r"(al));
                    }
                    const int chunk = chunk0 + kx;
                    const unsigned* wh = wf + ((size_t)((chunk * 2 + 0) * 4 + ks) * NT) * 64;
                    const unsigned* wl = wf + ((size_t)((chunk * 2 + 1) * 4 + ks) * NT) * 64;
#pragma unroll
                    for (int j = 0; j < HNT; j++) {
                        int nt = nw * HNT + j;
                        if (nt >= NT) break;
                        uint2 bh = *(const uint2*)(wh + (size_t)nt * 64 + lane * 2);
                        uint2 bl = *(const uint2*)(wl + (size_t)nt * 64 + lane * 2);
#pragma unroll
                        for (int mt = 0; mt < 2; mt++) {
                            MMA_BF16(acc[mt][j], Ah[mt], bh.x, bh.y);
                            MMA_BF16(acc[mt][j], Ah[mt], bl.x, bl.y);
                            MMA_BF16(acc[mt][j], Al[mt], bh.x, bh.y);
                        }
                    }
                }
            }
        }
    }

    // ---- epilogue: NCHW fp32 ----
#pragma unroll
    for (int mt = 0; mt < 2; mt++) {
        int prow = mw * 32 + mt * 16 + (lane >> 2);
#pragma unroll
        for (int j = 0; j < HNT; j++) {
            int nt = nw * HNT + j;
            if (nt >= NT) break;
            int cout = nt * 8 + ((lane & 3) << 1);
#pragma unroll
            for (int q = 0; q < 4; q++) {
                int co = cout + (q & 1);
                if (co >= Cout) continue;
                int pr = prow + ((q >> 1) << 3);
                float v = acc[mt][j][q] + __ldg(&bias[co]);
                if (relu) v = fmaxf(v, 0.f);
                outC[((size_t)(b * Cout + co)) * HW + (size_t)y * IMG + x0 + pr] = v;
            }
        }
    }
    (void)r0; (void)r1;
}

// ================= SIMT conv (Cin=3 only), NHWC fp32 output =================
#define TWs 32
#define THs 16
#define COUT_PTs 8
template <int ACT>   // 1 relu, 2 lrelu(0.1)
__global__ __launch_bounds__(256, 4)
void conv3_simt(const float* __restrict__ in, const float* __restrict__ wgt,
                const float* __restrict__ bias, float* __restrict__ out)
{
    __shared__ float s_in[3][THs + 2][36];
    __shared__ float s_w[COUT_PTs][3][12];
    const int tx = threadIdx.x, ty = threadIdx.y;
    const int tid = ty * 16 + tx;
    const int cx = tx * 2;
    const int w0 = blockIdx.x * TWs;
    const int by = blockIdx.y;
    const int b = by >> 4;
    const int h0 = (by & 15) * THs;
    const int coBase = blockIdx.z * COUT_PTs;
    float acc[COUT_PTs * 2];
#pragma unroll
    for (int i = 0; i < COUT_PTs * 2; i++) acc[i] = 0.f;

    for (int ci = 0; ci < 3; ci++) {
        const float* ip = in + (size_t)(b * 3 + ci) * HW;
        for (int j = tid; j < (THs + 2) * (TWs + 2); j += 256) {
            int r = j / (TWs + 2), c = j - r * (TWs + 2);
            int hh = h0 - 1 + r, ww = w0 - 1 + c;
            float v = 0.f;
            if (hh >= 0 && hh < IMG && ww >= 0 && ww < IMG) v = ip[hh * IMG + ww];
            s_in[ci][r][c] = v;
        }
    }
    if (tid < COUT_PTs * 27) {
        int co = tid / 27, rem2 = tid % 27, ci = rem2 / 9, k = rem2 % 9;
        s_w[co][ci][k] = wgt[((size_t)(coBase + co) * 3 + ci) * 9 + k];
    }
    __syncthreads();

    for (int ci = 0; ci < 3; ci++) {
        float2 r0a = *(const float2*)&s_in[ci][ty + 0][cx];
        float2 r0b = *(const float2*)&s_in[ci][ty + 0][cx + 2];
        float2 r1a = *(const float2*)&s_in[ci][ty + 1][cx];
        float2 r1b = *(const float2*)&s_in[ci][ty + 1][cx + 2];
        float2 r2a = *(const float2*)&s_in[ci][ty + 2][cx];
        float2 r2b = *(const float2*)&s_in[ci][ty + 2][cx + 2];
#pragma unroll
        for (int co = 0; co < COUT_PTs; co++) {
            float4 wa = *(const float4*)&s_w[co][ci][0];
            float4 wb = *(const float4*)&s_w[co][ci][4];
            float w8 = s_w[co][ci][8];
            float s0 = acc[co * 2], s1 = acc[co * 2 + 1];
            s0 += r0a.x * wa.x;  s1 += r0a.y * wa.x;
            s0 += r0a.y * wa.y;  s1 += r0b.x * wa.y;
            s0 += r0b.x * wa.z;  s1 += r0b.y * wa.z;
            s0 += r1a.x * wa.w;  s1 += r1a.y * wa.w;
            s0 += r1a.y * wb.x;  s1 += r1b.x * wb.x;
            s0 += r1b.x * wb.y;  s1 += r1b.y * wb.y;
            s0 += r2a.x * wb.z;  s1 += r2a.y * wb.z;
            s0 += r2a.y * wb.w;  s1 += r2b.x * wb.w;
            s0 += r2b.x * w8;    s1 += r2b.y * w8;
            acc[co * 2] = s0; acc[co * 2 + 1] = s1;
        }
    }
    const int hh = h0 + ty, ww = w0 + cx;
    const size_t pix = (size_t)b * HW + (size_t)hh * IMG + ww;
#pragma unroll
    for (int co = 0; co < COUT_PTs; co++) {
        int cog = coBase + co;
        float v0 = acc[co * 2], v1 = acc[co * 2 + 1];
        float bb = __ldg(&bias[cog]);
        v0 += bb; v1 += bb;
        if (ACT == 1) { v0 = fmaxf(v0, 0.f); v1 = fmaxf(v1, 0.f); }
        else { v0 = (v0 >= 0.f) ? v0 : 0.1f * v0; v1 = (v1 >= 0.f) ? v1 : 0.1f * v1; }
        out[pix * 64 + cog] = v0;
        out[(pix + 1) * 64 + cog] = v1;
    }
}

// ================= KPN: per-pixel 5x5 kernels + residual =================
__global__ void kpn_kernel(const float* __restrict__ x, const float* __restrict__ core,
                           const float* __restrict__ res, float* __restrict__ out)
{
    int idx = blockIdx.x * blockDim.x + threadIdx.x;
    if (idx >= BATCH * 3 * HW) return;
    int w = idx & (IMG - 1);
    int h = (idx >> 8) & (IMG - 1);
    int bc = idx >> 16;
    int c = bc % 3, b = bc / 3;
    const float* xp = x + (size_t)bc * HW;
    const float* cp = core + (size_t)(b * 75 + c * 25) * HW + h * IMG + w;
    float s = 0.f;
#pragma unroll
    for (int ky = 0; ky < 5; ky++) {
        int hh = h + ky - 2;
#pragma unroll
        for (int kx = 0; kx < 5; kx++) {
            int ww = w + kx - 2;
            float xv = (hh >= 0 && hh < IMG && ww >= 0 && ww < IMG) ? xp[hh * IMG + ww] : 0.f;
            s += xv * cp[(ky * 5 + kx) * HW];
        }
    }
    out[idx] = s + res[idx];
}

// ================= host =================
extern "C" void kernel_launch(void* const* d_in, const int* in_sizes, int n_in,
                              void* d_out, int out_size)
{
    const float* x       = (const float*)d_in[0];
    const float* w_first = (const float*)d_in[1];
    const float* b_first = (const float*)d_in[2];
    const float* w_trunk = (const float*)d_in[3];
    const float* b_trunk = (const float*)d_in[4];
    const float* c1_w    = (const float*)d_in[5];
    const float* c1_b    = (const float*)d_in[6];
    const float* c2_w1   = (const float*)d_in[7];
    const float* c2_b1   = (const float*)d_in[8];
    const float* c2_w2   = (const float*)d_in[9];
    const float* c2_b2   = (const float*)d_in[10];
    const float* c3_w1   = (const float*)d_in[11];
    const float* c3_b1   = (const float*)d_in[12];
    const float* c3_w2   = (const float*)d_in[13];
    const float* c3_b2   = (const float*)d_in[14];
    const float* c3_w3   = (const float*)d_in[15];
    const float* c3_b3   = (const float*)d_in[16];
    float* out = (float*)d_out;
    (void)in_sizes; (void)n_in; (void)out_size;

    float *nhwc, *core, *res;
    unsigned* wf;
    cudaGetSymbolAddress((void**)&nhwc, g_nhwc);
    cudaGetSymbolAddress((void**)&core, g_core);
    cudaGetSymbolAddress((void**)&res,  g_res);
    cudaGetSymbolAddress((void**)&wf,   g_wfrag);
    const size_t PL = (size_t)NPIX * 64;
    float* fea = nhwc;
    float* bA  = nhwc + PL;
    float* bB  = nhwc + 2 * PL;
    float* bT  = nhwc + 3 * PL;

    // ---- weight prep (fragment-ordered bf16 hi/lo) ----
    for (int j = 0; j < 32; j++)
        prep_w<<<(36864 + 255) / 256, 256>>>(w_trunk + (size_t)j * 36864, wf + WF_TRUNK(j), 64, 64, 8, 36864);
    prep_w<<<(36864 + 255) / 256, 256>>>(c3_w2, wf + WF_C3W2, 64, 64, 8, 36864);
    prep_w<<<(36864 + 255) / 256, 256>>>(c3_w3, wf + WF_C3W3, 64, 64, 8, 36864);
    prep_w<<<(73728 + 255) / 256, 256>>>(c2_w1, wf + WF_C2W1, 64, 128, 8, 73728);
    prep_w<<<(92160 + 255) / 256, 256>>>(c1_w,  wf + WF_C1,   75, 128, 10, 92160);
    prep_w<<<(4608  + 255) / 256, 256>>>(c2_w2, wf + WF_C2W2,  3,  64,  1, 4608);

    dim3 sgrid(IMG / TWs, (IMG / THs) * BATCH, 8);
    dim3 sblk(16, 16);

    // 1) fea1 = lrelu(conv_first(x))
    conv3_simt<2><<<sgrid, sblk>>>(x, w_first, b_first, fea);

    // 2) 16 residual blocks on tensor cores (2-row kernel)
    float* cur = fea;
    for (int i = 0; i < 16; i++) {
        float* dst = (i & 1) ? bB : bA;
        const float* extra = (i == 15) ? fea : nullptr;
        tc_conv2<<<1024, 256>>>(cur, nullptr, wf + WF_TRUNK(2 * i), b_trunk + (size_t)(2 * i) * 64,
                                bT, nullptr, nullptr, 1);
        tc_conv2<<<1024, 256>>>(bT, nullptr, wf + WF_TRUNK(2 * i + 1), b_trunk + (size_t)(2 * i + 1) * 64,
                                dst, cur, extra, 0);
        cur = dst;
    }
    // cur = bB (i=15). free: bA, bT.

    // 3) image branch: t1 (SIMT) -> t2 -> t3
    conv3_simt<1><<<sgrid, sblk>>>(x, c3_w1, c3_b1, bT);
    tc_conv2<<<1024, 256>>>(bT, nullptr, wf + WF_C3W2, c3_b2, bA, nullptr, nullptr, 1);
    tc_conv2<<<1024, 256>>>(bA, nullptr, wf + WF_C3W3, c3_b3, bT, nullptr, nullptr, 0); // t3=bT

    // 4) R1 = relu(conv(concat[t3,F], c2_w1)) -> bA ; res = conv(R1, c2_w2) (NCHW)
    tc_conv2<<<1024, 256>>>(bT, cur, wf + WF_C2W1, c2_b1, bA, nullptr, nullptr, 1);
    tc_conv<1><<<2048, 256>>>(bA, nullptr, wf + WF_C2W2, c2_b2, nullptr, nullptr, res, 3, 0);

    // 5) core = conv(concat[t3,F], c1_w) (NCHW)
    tc_conv<10><<<2048, 256>>>(bT, cur, wf + WF_C1, c1_b, nullptr, nullptr, core, 75, 0);

    // 6) KPN + residual
    kpn_kernel<<<(BATCH * 3 * HW + 255) / 256, 256>>>(x, core, res, out);
}

// round 15
// speedup vs baseline: 6.2264x; 1.0219x over previous
#include <cuda_runtime.h>
#include <cuda_bf16.h>
#include <cstdint>

// ================= problem constants =================
#define IMG 256
#define BATCH 4
#define HW 65536
#define NPIX 262144          // BATCH*HW

// ================= device scratch (no allocs) =================
// NHWC fp32 planes: 0=fea1 1=bufA 2=bufB 3=bufT
__device__ __align__(16) float g_nhwc[4][(size_t)NPIX * 64];
__device__ float g_core[(size_t)BATCH * 75 * HW];
__device__ float g_res [(size_t)BATCH * 3  * HW];
// fragment-ordered bf16 weights (u32 elements)
#define WF_TRUNK(j) ((size_t)(j) * 36864)
#define WF_C3W2  1179648
#define WF_C3W3  1216512
#define WF_C2W1  1253376
#define WF_C1    1327104
#define WF_C2W2  1419264
#define WF_TOTAL 1423872
__device__ __align__(16) unsigned g_wfrag[WF_TOTAL];

// ================= helpers =================
__device__ __forceinline__ unsigned smem_u32(const void* p) {
    unsigned a;
    asm("{ .reg .u64 t; cvta.to.shared.u64 t, %1; cvt.u32.u64 %0, t; }" : "=r"(a) : "l"(p));
    return a;
}
__device__ __forceinline__ unsigned pk(__nv_bfloat16 a, __nv_bfloat16 b) {
    return (unsigned)__bfloat16_as_ushort(a) | ((unsigned)__bfloat16_as_ushort(b) << 16);
}
#define MMA_BF16(acc, a, b0, b1)                                              \
    asm volatile(                                                             \
        "mma.sync.aligned.m16n8k16.row.col.f32.bf16.bf16.f32 "               \
        "{%0,%1,%2,%3}, {%4,%5,%6,%7}, {%8,%9}, {%0,%1,%2,%3};"              \
        : "+f"((acc)[0]), "+f"((acc)[1]), "+f"((acc)[2]), "+f"((acc)[3])      \
        : "r"((a)[0]), "r"((a)[1]), "r"((a)[2]), "r"((a)[3]),                 \
          "r"(b0), "r"(b1))

// ================= merged weight prep: all layers in ONE launch =================
// per-segment formula identical to R12/R14 prep_w.
__device__ __forceinline__ void prep_one(const float* __restrict__ w, unsigned* __restrict__ dst,
                                         int idx, int Cout, int CinW, int NT)
{
    int lane2 = idx & 63;
    int lane = lane2 >> 1, r = lane2 & 1;
    int tmp = idx >> 6;
    int ntile = tmp % NT; tmp /= NT;
    int kstep = tmp & 3; tmp >>= 2;
    int term = tmp & 1;
    int chunk = tmp >> 1;
    int src = chunk / 9, t9 = chunk % 9, ky = t9 / 3, kx = t9 % 3;
    int n = ntile * 8 + (lane >> 2);
    int k = kstep * 16 + ((lane & 3) << 1) + 8 * r;
    int ci = src * 64 + k;
    float v0 = 0.f, v1 = 0.f;
    if (n < Cout) {
        if (ci < CinW)     v0 = w[(((size_t)n * CinW + ci) * 3 + ky) * 3 + kx];
        if (ci + 1 < CinW) v1 = w[(((size_t)n * CinW + ci + 1) * 3 + ky) * 3 + kx];
    }
    __nv_bfloat16 h0 = __float2bfloat16(v0), h1 = __float2bfloat16(v1);
    unsigned outv;
    if (term == 0) outv = pk(h0, h1);
    else outv = pk(__float2bfloat16(v0 - __bfloat162float(h0)),
                   __float2bfloat16(v1 - __bfloat162float(h1)));
    dst[idx] = outv;
}

__global__ void prep_all(const float* __restrict__ w_trunk,
                         const float* __restrict__ c3_w2, const float* __restrict__ c3_w3,
                         const float* __restrict__ c2_w1, const float* __restrict__ c1_w,
                         const float* __restrict__ c2_w2, unsigned* __restrict__ wf)
{
    int g = blockIdx.x * 256 + threadIdx.x;
    if (g >= WF_TOTAL) return;
    if (g < WF_C3W2) {
        int j = g / 36864;
        prep_one(w_trunk + (size_t)j * 36864, wf + WF_TRUNK(j), g % 36864, 64, 64, 8);
    } else if (g < WF_C3W3) {
        prep_one(c3_w2, wf + WF_C3W2, g - WF_C3W2, 64, 64, 8);
    } else if (g < WF_C2W1) {
        prep_one(c3_w3, wf + WF_C3W3, g - WF_C3W3, 64, 64, 8);
    } else if (g < WF_C1) {
        prep_one(c2_w1, wf + WF_C2W1, g - WF_C2W1, 64, 128, 8);
    } else if (g < WF_C2W2) {
        prep_one(c1_w, wf + WF_C1, g - WF_C1, 75, 128, 10);
    } else {
        prep_one(c2_w2, wf + WF_C2W2, g - WF_C2W2, 3, 64, 1);
    }
}

// ======== 2-row tensor-core implicit-GEMM 3x3 conv (mma.sync bf16, 3-term) ========
// CTA: 2 output rows x 128 pixels x 64 couts. 8 warps: 4 M x 2 N.
// B fragments prefetched into registers before each MMA burst.
__global__ __launch_bounds__(256, 2)
void tc_conv2(const float* __restrict__ a0, const float* __restrict__ a1,
              const unsigned* __restrict__ wf, const float* __restrict__ bias,
              float* __restrict__ outN,
              const float* __restrict__ r0, const float* __restrict__ r1, int relu)
{
    constexpr int NT = 8, HNT = 4;
    __shared__ __nv_bfloat16 sA[2][130][72];   // [hi/lo][slot][ci] stride 144B
    const int tid = threadIdx.x;
    const int lane = tid & 31, wid = tid >> 5;
    const int mw = wid & 3, nw = wid >> 2;
    const int t = blockIdx.x;
    const int b = t >> 8, rem = t & 255;
    const int y0 = (rem >> 1) << 1, x0 = (rem & 1) << 7;
    const int nSrc = (a1 != nullptr) ? 2 : 1;
    // invariant per-thread B base: + nt0*64 + lane*2
    const unsigned* wfL = wf + (size_t)(nw * HNT) * 64 + lane * 2;

    float acc[2][2][HNT][4];                   // [outrow][mt][nt][4]
#pragma unroll
    for (int o = 0; o < 2; o++)
#pragma unroll
        for (int mt = 0; mt < 2; mt++)
#pragma unroll
            for (int j = 0; j < HNT; j++)
#pragma unroll
                for (int q = 0; q < 4; q++) acc[o][mt][j][q] = 0.f;

    for (int src = 0; src < nSrc; src++) {
        const float* ap = src ? a1 : a0;
        for (int r = y0 - 1; r <= y0 + 2; r++) {
            if (r < 0 || r >= IMG) continue;
            __syncthreads();
            // ---- fill smem with input row r (slots 0..129 = x0-1..x0+128), hi/lo ----
            const float* rowp = ap + ((size_t)b * HW + (size_t)r * IMG) * 64;
            for (int i = tid; i < 130 * 16; i += 256) {
                int slot = i >> 4, cg = (i & 15) << 2;
                int ax = x0 - 1 + slot;
                float4 f = (ax >= 0 && ax < IMG)
                         ? *(const float4*)(rowp + (size_t)ax * 64 + cg)
                         : make_float4(0.f, 0.f, 0.f, 0.f);
                __nv_bfloat16 h0 = __float2bfloat16(f.x), h1 = __float2bfloat16(f.y);
                __nv_bfloat16 h2 = __float2bfloat16(f.z), h3 = __float2bfloat16(f.w);
                *(unsigned*)&sA[0][slot][cg]     = pk(h0, h1);
                *(unsigned*)&sA[0][slot][cg + 2] = pk(h2, h3);
                *(unsigned*)&sA[1][slot][cg]     = pk(__float2bfloat16(f.x - __bfloat162float(h0)),
                                                      __float2bfloat16(f.y - __bfloat162float(h1)));
                *(unsigned*)&sA[1][slot][cg + 2] = pk(__float2bfloat16(f.z - __bfloat162float(h2)),
                                                      __float2bfloat16(f.w - __bfloat162float(h3)));
            }
            __syncthreads();
            const int ky0 = r - y0 + 1;          // tap for outrow 0
            const int ky1 = r - y0;              // tap for outrow 1
            const bool v0ok = (ky0 <= 2);
            const bool v1ok = (ky1 >= 0);
#pragma unroll
            for (int kx = 0; kx < 3; kx++) {
                // chunk bases (u32 units): chunk*2*4*NT*64 = chunk*4096
                const unsigned* cb0 = wfL + (size_t)(src * 9 + ky0 * 3 + kx) * 4096;
                const unsigned* cb1 = wfL + (size_t)(src * 9 + ky1 * 3 + kx) * 4096;
#pragma unroll
                for (int ks = 0; ks < 4; ks++) {
                    // ---- A fragments once: hi and lo planes, both m-tiles ----
                    unsigned Ah[2][4], Al[2][4];
#pragma unroll
                    for (int mt = 0; mt < 2; mt++) {
                        int slot = mw * 32 + mt * 16 + (lane & 15) + kx;
                        int kh = ks * 16 + ((lane >> 4) << 3);
                        unsigned ah = smem_u32(&sA[0][slot][kh]);
                        asm volatile("ldmatrix.sync.aligned.m8n8.x4.shared.b16 "
                                     "{%0,%1,%2,%3}, [%4];"
                                     : "=r"(Ah[mt][0]), "=r"(Ah[mt][1]),
                                       "=r"(Ah[mt][2]), "=r"(Ah[mt][3]) : "r"(ah));
                        unsigned al = smem_u32(&sA[1][slot][kh]);
                        asm volatile("ldmatrix.sync.aligned.m8n8.x4.shared.b16 "
                                     "{%0,%1,%2,%3}, [%4];"
                                     : "=r"(Al[mt][0]), "=r"(Al[mt][1]),
                                       "=r"(Al[mt][2]), "=r"(Al[mt][3]) : "r"(al));
                    }
                    // ---- MMA blocks per valid output row, B prefetched ----
#pragma unroll
                    for (int o = 0; o < 2; o++) {
                        if (o == 0 ? !v0ok : !v1ok) continue;
                        const unsigned* cb = (o == 0) ? cb0 : cb1;
                        const unsigned* wh = cb + ks * 512;          // term 0
                        const unsigned* wl = cb + 2048 + ks * 512;   // term 1
                        uint2 bh[HNT], bl[HNT];
#pragma unroll
                        for (int j = 0; j < HNT; j++) {
                            bh[j] = __ldg((const uint2*)(wh + (size_t)j * 64));
                            bl[j] = __ldg((const uint2*)(wl + (size_t)j * 64));
                        }
#pragma unroll
                        for (int j = 0; j < HNT; j++) {
#pragma unroll
                            for (int mt = 0; mt < 2; mt++) {
                                MMA_BF16(acc[o][mt][j], Ah[mt], bh[j].x, bh[j].y);
                                MMA_BF16(acc[o][mt][j], Ah[mt], bl[j].x, bl[j].y);
                                MMA_BF16(acc[o][mt][j], Al[mt], bh[j].x, bh[j].y);
                            }
                        }
                    }
                }
            }
        }
    }

    // ---- epilogue: both output rows ----
#pragma unroll
    for (int o = 0; o < 2; o++) {
        const size_t pixB = (size_t)b * HW + (size_t)(y0 + o) * IMG + x0;
#pragma unroll
        for (int mt = 0; mt < 2; mt++) {
            int prow = mw * 32 + mt * 16 + (lane >> 2);
#pragma unroll
            for (int j = 0; j < HNT; j++) {
                int nt = nw * HNT + j;
                int cout = nt * 8 + ((lane & 3) << 1);
                float2 bb = *(const float2*)&bias[cout];
                float v0 = acc[o][mt][j][0] + bb.x, v1 = acc[o][mt][j][1] + bb.y;
                float v2 = acc[o][mt][j][2] + bb.x, v3 = acc[o][mt][j][3] + bb.y;
                if (relu) {
                    v0 = fmaxf(v0, 0.f); v1 = fmaxf(v1, 0.f);
                    v2 = fmaxf(v2, 0.f); v3 = fmaxf(v3, 0.f);
                }
                size_t i0 = (pixB + prow) * 64 + cout;
                size_t i1 = (pixB + prow + 8) * 64 + cout;
                if (r0) {
                    float2 q = *(const float2*)&r0[i0]; v0 += q.x; v1 += q.y;
                    q = *(const float2*)&r0[i1]; v2 += q.x; v3 += q.y;
                }
                if (r1) {
                    float2 q = *(const float2*)&r1[i0]; v0 += q.x; v1 += q.y;
                    q = *(const float2*)&r1[i1]; v2 += q.x; v3 += q.y;
                }
                *(float2*)&outN[i0] = make_float2(v0, v1);
                *(float2*)&outN[i1] = make_float2(v2, v3);
            }
        }
    }
}

// ======== 1-row variant (NCHW outputs: core/res), proven in R12 ========
template <int NT>
__global__ __launch_bounds__(256)
void tc_conv(const float* __restrict__ a0, const float* __restrict__ a1,
             const unsigned* __restrict__ wf, const float* __restrict__ bias,
             float* __restrict__ outC, int Cout, int relu)
{
    constexpr int HNT = (NT + 1) / 2;
    __shared__ __nv_bfloat16 sA[2][130][72];
    const int tid = threadIdx.x;
    const int lane = tid & 31, wid = tid >> 5;
    const int mw = wid & 3, nw = wid >> 2;
    const int t = blockIdx.x;
    const int b = t >> 9, rem = t & 511, y = rem >> 1, x0 = (rem & 1) << 7;
    const int nSrc = (a1 != nullptr) ? 2 : 1;

    float acc[2][HNT][4];
#pragma unroll
    for (int mt = 0; mt < 2; mt++)
#pragma unroll
        for (int j = 0; j < HNT; j++)
#pragma unroll
            for (int q = 0; q < 4; q++) acc[mt][j][q] = 0.f;

    for (int src = 0; src < nSrc; src++) {
        const float* ap = src ? a1 : a0;
        for (int ky = 0; ky < 3; ky++) {
            int yy = y + ky - 1;
            if (yy < 0 || yy >= IMG) continue;
            __syncthreads();
            const float* rowp = ap + ((size_t)b * HW + (size_t)yy * IMG) * 64;
            for (int i = tid; i < 130 * 16; i += 256) {
                int slot = i >> 4, cg = (i & 15) << 2;
                int ax = x0 - 1 + slot;
                float4 f = (ax >= 0 && ax < IMG)
                         ? *(const float4*)(rowp + (size_t)ax * 64 + cg)
                         : make_float4(0.f, 0.f, 0.f, 0.f);
                __nv_bfloat16 h0 = __float2bfloat16(f.x), h1 = __float2bfloat16(f.y);
                __nv_bfloat16 h2 = __float2bfloat16(f.z), h3 = __float2bfloat16(f.w);
                *(unsigned*)&sA[0][slot][cg]     = pk(h0, h1);
                *(unsigned*)&sA[0][slot][cg + 2] = pk(h2, h3);
                *(unsigned*)&sA[1][slot][cg]     = pk(__float2bfloat16(f.x - __bfloat162float(h0)),
                                                      __float2bfloat16(f.y - __bfloat162float(h1)));
                *(unsigned*)&sA[1][slot][cg + 2] = pk(__float2bfloat16(f.z - __bfloat162float(h2)),
                                                      __float2bfloat16(f.w - __bfloat162float(h3)));
            }
            __syncthreads();
            const int chunk0 = src * 9 + ky * 3;
#pragma unroll
            for (int kx = 0; kx < 3; kx++) {
#pragma unroll
                for (int ks = 0; ks < 4; ks++) {
                    unsigned Ah[2][4], Al[2][4];
#pragma unroll
                    for (int mt = 0; mt < 2; mt++) {
                        int slot = mw * 32 + mt * 16 + (lane & 15) + kx;
                        int kh = ks * 16 + ((lane >> 4) << 3);
                        unsigned ah = smem_u32(&sA[0][slot][kh]);
                        asm volatile("ldmatrix.sync.aligned.m8n8.x4.shared.b16 "
                                     "{%0,%1,%2,%3}, [%4];"
                                     : "=r"(Ah[mt][0]), "=r"(Ah[mt][1]),
                                       "=r"(Ah[mt][2]), "=r"(Ah[mt][3]) : "r"(ah));
                        unsigned al = smem_u32(&sA[1][slot][kh]);
                        asm volatile("ldmatrix.sync.aligned.m8n8.x4.shared.b16 "
                                     "{%0,%1,%2,%3}, [%4];"
                                     : "=r"(Al[mt][0]), "=r"(Al[mt][1]),
                                       "=r"(Al[mt][2]), "=r"(Al[mt][3]) : "r"(al));
                    }
                    const int chunk = chunk0 + kx;
                    const unsigned* wh = wf + ((size_t)((chunk * 2 + 0) * 4 + ks) * NT) * 64;
                    const unsigned* wl = wf + ((size_t)((chunk * 2 + 1) * 4 + ks) * NT) * 64;
#pragma unroll
                    for (int j = 0; j < HNT; j++) {
                        int nt = nw * HNT + j;
                        if (nt >= NT) break;
                        uint2 bh = __ldg((const uint2*)(wh + (size_t)nt * 64 + lane * 2));
                        uint2 bl = __ldg((const uint2*)(wl + (size_t)nt * 64 + lane * 2));
#pragma unroll
                        for (int mt = 0; mt < 2; mt++) {
                            MMA_BF16(acc[mt][j], Ah[mt], bh.x, bh.y);
                            MMA_BF16(acc[mt][j], Ah[mt], bl.x, bl.y);
                            MMA_BF16(acc[mt][j], Al[mt], bh.x, bh.y);
                        }
                    }
                }
            }
        }
    }

    // ---- epilogue: NCHW fp32 ----
#pragma unroll
    for (int mt = 0; mt < 2; mt++) {
        int prow = mw * 32 + mt * 16 + (lane >> 2);
#pragma unroll
        for (int j = 0; j < HNT; j++) {
            int nt = nw * HNT + j;
            if (nt >= NT) break;
            int cout = nt * 8 + ((lane & 3) << 1);
#pragma unroll
            for (int q = 0; q < 4; q++) {
                int co = cout + (q & 1);
                if (co >= Cout) continue;
                int pr = prow + ((q >> 1) << 3);
                float v = acc[mt][j][q] + __ldg(&bias[co]);
                if (relu) v = fmaxf(v, 0.f);
                outC[((size_t)(b * Cout + co)) * HW + (size_t)y * IMG + x0 + pr] = v;
            }
        }
    }
}

// ================= SIMT conv (Cin=3 only), NHWC fp32 output =================
#define TWs 32
#define THs 16
#define COUT_PTs 8
template <int ACT>   // 1 relu, 2 lrelu(0.1)
__global__ __launch_bounds__(256, 4)
void conv3_simt(const float* __restrict__ in, const float* __restrict__ wgt,
                const float* __restrict__ bias, float* __restrict__ out)
{
    __shared__ float s_in[3][THs + 2][36];
    __shared__ float s_w[COUT_PTs][3][12];
    const int tx = threadIdx.x, ty = threadIdx.y;
    const int tid = ty * 16 + tx;
    const int cx = tx * 2;
    const int w0 = blockIdx.x * TWs;
    const int by = blockIdx.y;
    const int b = by >> 4;
    const int h0 = (by & 15) * THs;
    const int coBase = blockIdx.z * COUT_PTs;
    float acc[COUT_PTs * 2];
#pragma unroll
    for (int i = 0; i < COUT_PTs * 2; i++) acc[i] = 0.f;

    for (int ci = 0; ci < 3; ci++) {
        const float* ip = in + (size_t)(b * 3 + ci) * HW;
        for (int j = tid; j < (THs + 2) * (TWs + 2); j += 256) {
            int r = j / (TWs + 2), c = j - r * (TWs + 2);
            int hh = h0 - 1 + r, ww = w0 - 1 + c;
            float v = 0.f;
            if (hh >= 0 && hh < IMG && ww >= 0 && ww < IMG) v = ip[hh * IMG + ww];
            s_in[ci][r][c] = v;
        }
    }
    if (tid < COUT_PTs * 27) {
        int co = tid / 27, rem2 = tid % 27, ci = rem2 / 9, k = rem2 % 9;
        s_w[co][ci][k] = wgt[((size_t)(coBase + co) * 3 + ci) * 9 + k];
    }
    __syncthreads();

    for (int ci = 0; ci < 3; ci++) {
        float2 r0a = *(const float2*)&s_in[ci][ty + 0][cx];
        float2 r0b = *(const float2*)&s_in[ci][ty + 0][cx + 2];
        float2 r1a = *(const float2*)&s_in[ci][ty + 1][cx];
        float2 r1b = *(const float2*)&s_in[ci][ty + 1][cx + 2];
        float2 r2a = *(const float2*)&s_in[ci][ty + 2][cx];
        float2 r2b = *(const float2*)&s_in[ci][ty + 2][cx + 2];
#pragma unroll
        for (int co = 0; co < COUT_PTs; co++) {
            float4 wa = *(const float4*)&s_w[co][ci][0];
            float4 wb = *(const float4*)&s_w[co][ci][4];
            float w8 = s_w[co][ci][8];
            float s0 = acc[co * 2], s1 = acc[co * 2 + 1];
            s0 += r0a.x * wa.x;  s1 += r0a.y * wa.x;
            s0 += r0a.y * wa.y;  s1 += r0b.x * wa.y;
            s0 += r0b.x * wa.z;  s1 += r0b.y * wa.z;
            s0 += r1a.x * wa.w;  s1 += r1a.y * wa.w;
            s0 += r1a.y * wb.x;  s1 += r1b.x * wb.x;
            s0 += r1b.x * wb.y;  s1 += r1b.y * wb.y;
            s0 += r2a.x * wb.z;  s1 += r2a.y * wb.z;
            s0 += r2a.y * wb.w;  s1 += r2b.x * wb.w;
            s0 += r2b.x * w8;    s1 += r2b.y * w8;
            acc[co * 2] = s0; acc[co * 2 + 1] = s1;
        }
    }
    const int hh = h0 + ty, ww = w0 + cx;
    const size_t pix = (size_t)b * HW + (size_t)hh * IMG + ww;
#pragma unroll
    for (int co = 0; co < COUT_PTs; co++) {
        int cog = coBase + co;
        float v0 = acc[co * 2], v1 = acc[co * 2 + 1];
        float bb = __ldg(&bias[cog]);
        v0 += bb; v1 += bb;
        if (ACT == 1) { v0 = fmaxf(v0, 0.f); v1 = fmaxf(v1, 0.f); }
        else { v0 = (v0 >= 0.f) ? v0 : 0.1f * v0; v1 = (v1 >= 0.f) ? v1 : 0.1f * v1; }
        out[pix * 64 + cog] = v0;
        out[(pix + 1) * 64 + cog] = v1;
    }
}

// ================= KPN: per-pixel 5x5 kernels + residual =================
__global__ void kpn_kernel(const float* __restrict__ x, const float* __restrict__ core,
                           const float* __restrict__ res, float* __restrict__ out)
{
    int idx = blockIdx.x * blockDim.x + threadIdx.x;
    if (idx >= BATCH * 3 * HW) return;
    int w = idx & (IMG - 1);
    int h = (idx >> 8) & (IMG - 1);
    int bc = idx >> 16;
    int c = bc % 3, b = bc / 3;
    const float* xp = x + (size_t)bc * HW;
    const float* cp = core + (size_t)(b * 75 + c * 25) * HW + h * IMG + w;
    float s = 0.f;
#pragma unroll
    for (int ky = 0; ky < 5; ky++) {
        int hh = h + ky - 2;
#pragma unroll
        for (int kx = 0; kx < 5; kx++) {
            int ww = w + kx - 2;
            float xv = (hh >= 0 && hh < IMG && ww >= 0 && ww < IMG) ? xp[hh * IMG + ww] : 0.f;
            s += xv * cp[(ky * 5 + kx) * HW];
        }
    }
    out[idx] = s + res[idx];
}

// ================= host =================
extern "C" void kernel_launch(void* const* d_in, const int* in_sizes, int n_in,
                              void* d_out, int out_size)
{
    const float* x       = (const float*)d_in[0];
    const float* w_first = (const float*)d_in[1];
    const float* b_first = (const float*)d_in[2];
    const float* w_trunk = (const float*)d_in[3];
    const float* b_trunk = (const float*)d_in[4];
    const float* c1_w    = (const float*)d_in[5];
    const float* c1_b    = (const float*)d_in[6];
    const float* c2_w1   = (const float*)d_in[7];
    const float* c2_b1   = (const float*)d_in[8];
    const float* c2_w2   = (const float*)d_in[9];
    const float* c2_b2   = (const float*)d_in[10];
    const float* c3_w1   = (const float*)d_in[11];
    const float* c3_b1   = (const float*)d_in[12];
    const float* c3_w2   = (const float*)d_in[13];
    const float* c3_b2   = (const float*)d_in[14];
    const float* c3_w3   = (const float*)d_in[15];
    const float* c3_b3   = (const float*)d_in[16];
    float* out = (float*)d_out;
    (void)in_sizes; (void)n_in; (void)out_size;

    float *nhwc, *core, *res;
    unsigned* wf;
    cudaGetSymbolAddress((void**)&nhwc, g_nhwc);
    cudaGetSymbolAddress((void**)&core, g_core);
    cudaGetSymbolAddress((void**)&res,  g_res);
    cudaGetSymbolAddress((void**)&wf,   g_wfrag);
    const size_t PL = (size_t)NPIX * 64;
    float* fea = nhwc;
    float* bA  = nhwc + PL;
    float* bB  = nhwc + 2 * PL;
    float* bT  = nhwc + 3 * PL;

    // ---- merged weight prep: ONE launch ----
    prep_all<<<(WF_TOTAL + 255) / 256, 256>>>(w_trunk, c3_w2, c3_w3, c2_w1, c1_w, c2_w2, wf);

    dim3 sgrid(IMG / TWs, (IMG / THs) * BATCH, 8);
    dim3 sblk(16, 16);

    // 1) fea1 = lrelu(conv_first(x))
    conv3_simt<2><<<sgrid, sblk>>>(x, w_first, b_first, fea);

    // 2) 16 residual blocks on tensor cores (2-row kernel)
    float* cur = fea;
    for (int i = 0; i < 16; i++) {
        float* dst = (i & 1) ? bB : bA;
        const float* extra = (i == 15) ? fea : nullptr;
        tc_conv2<<<1024, 256>>>(cur, nullptr, wf + WF_TRUNK(2 * i), b_trunk + (size_t)(2 * i) * 64,
                                bT, nullptr, nullptr, 1);
        tc_conv2<<<1024, 256>>>(bT, nullptr, wf + WF_TRUNK(2 * i + 1), b_trunk + (size_t)(2 * i + 1) * 64,
                                dst, cur, extra, 0);
        cur = dst;
    }
    // cur = bB (i=15). free: bA, bT.

    // 3) image branch: t1 (SIMT) -> t2 -> t3
    conv3_simt<1><<<sgrid, sblk>>>(x, c3_w1, c3_b1, bT);
    tc_conv2<<<1024, 256>>>(bT, nullptr, wf + WF_C3W2, c3_b2, bA, nullptr, nullptr, 1);
    tc_conv2<<<1024, 256>>>(bA, nullptr, wf + WF_C3W3, c3_b3, bT, nullptr, nullptr, 0); // t3=bT

    // 4) R1 = relu(conv(concat[t3,F], c2_w1)) -> bA ; res = conv(R1, c2_w2) (NCHW)
    tc_conv2<<<1024, 256>>>(bT, cur, wf + WF_C2W1, c2_b1, bA, nullptr, nullptr, 1);
    tc_conv<1><<<2048, 256>>>(bA, nullptr, wf + WF_C2W2, c2_b2, res, 3, 0);

    // 5) core = conv(concat[t3,F], c1_w) (NCHW)
    tc_conv<10><<<2048, 256>>>(bT, cur, wf + WF_C1, c1_b, core, 75, 0);

    // 6) KPN + residual
    kpn_kernel<<<(BATCH * 3 * HW + 255) / 256, 256>>>(x, core, res, out);
}